// round 11
// baseline (speedup 1.0000x reference)
#include <cuda_runtime.h>
#include <cuda_fp16.h>
#include <cstdint>

// ---------------- problem constants ----------------
#define B_  4
#define S_  2048
#define D_  1024
#define P_  256
#define H_  16
#define DH_ 64
#define DFF_ 512
#define M_  (B_*S_)           // 8192 rows
#define EPS_ 1e-6f

// ---------------- scratch (static device globals; no allocation) ----------------
__device__ float  g_xn [M_*D_];          // exact LN1 output (residual)
__device__ __half g_xnr[M_*D_];          // half LN1 output (GEMM A)
__device__ __half g_qkv[M_*3*D_];        // fused QKV output [M][3072]
__device__ __half g_vt [M_*D_];          // V transposed: [(b*H+h)*64+d][S]
__device__ __half g_ctx[M_*D_];
__device__ __half g_x2 [M_*D_];
__device__ __half g_hb [M_*DFF_];
__device__ __half g_xr [M_*D_];          // half copy of final x (Wp input)
__device__ __half g_pxh[M_*P_];
__device__ __half g_wqkvT[3*D_*D_];      // [3072][1024]
__device__ __half g_woT[D_*D_];
__device__ __half g_w1T[D_*DFF_];
__device__ __half g_w2T[DFF_*D_];
__device__ __half g_wpT[P_*(D_+P_)];     // [256][1280]
__device__ float  g_bqkv[3*D_];

// ---------------- ptx helpers ----------------
__device__ __forceinline__ void mma_f16(float c[4], const uint32_t a[4], const uint32_t b[2]) {
    asm volatile(
        "mma.sync.aligned.m16n8k16.row.col.f32.f16.f16.f32 "
        "{%0,%1,%2,%3}, {%4,%5,%6,%7}, {%8,%9}, {%0,%1,%2,%3};\n"
        : "+f"(c[0]), "+f"(c[1]), "+f"(c[2]), "+f"(c[3])
        : "r"(a[0]), "r"(a[1]), "r"(a[2]), "r"(a[3]), "r"(b[0]), "r"(b[1]));
}

__device__ __forceinline__ void ldsm4(uint32_t r[4], uint32_t addr) {
    asm volatile("ldmatrix.sync.aligned.m8n8.x4.shared.b16 {%0,%1,%2,%3}, [%4];"
        : "=r"(r[0]), "=r"(r[1]), "=r"(r[2]), "=r"(r[3]) : "r"(addr));
}

__device__ __forceinline__ uint32_t smem_u32(const void* p) {
    uint32_t a;
    asm("{ .reg .u64 t; cvta.to.shared.u64 t, %1; cvt.u32.u64 %0, t; }" : "=r"(a) : "l"(p));
    return a;
}

__device__ __forceinline__ void cp16(uint32_t dst, const void* src) {
    asm volatile("cp.async.ca.shared.global [%0], [%1], 16;" :: "r"(dst), "l"(src));
}
__device__ __forceinline__ void cp_commit() {
    asm volatile("cp.async.commit_group;" ::: "memory");
}
template<int N_>
__device__ __forceinline__ void cp_wait() {
    asm volatile("cp.async.wait_group %0;" :: "n"(N_) : "memory");
}

__device__ __forceinline__ uint32_t f2h2(float a, float b) {
    __half2 h = __floats2half2_rn(a, b);
    return *(uint32_t*)&h;
}

// ---------------- prep kernels ----------------
// Unified transpose+convert for all 7 weights: in[K][N] f32 -> out[N][K] half.
// z: 0 Wq, 1 Wk, 2 Wv (-> wqkvT slices), 3 Wo, 4 W1, 5 W2, 6 Wp.
__global__ void wtrans_all_kernel(const float* __restrict__ Wq, const float* __restrict__ Wk,
                                  const float* __restrict__ Wv, const float* __restrict__ Wo,
                                  const float* __restrict__ W1, const float* __restrict__ W2,
                                  const float* __restrict__ Wp,
                                  __half* __restrict__ oqkv, __half* __restrict__ owo,
                                  __half* __restrict__ ow1, __half* __restrict__ ow2,
                                  __half* __restrict__ owp) {
    const int z = blockIdx.z;
    const float* in; __half* out; int K, N;
    switch (z) {
        case 0: in = Wq; out = oqkv;             K = D_;    N = D_;   break;
        case 1: in = Wk; out = oqkv + D_*D_;     K = D_;    N = D_;   break;
        case 2: in = Wv; out = oqkv + 2*D_*D_;   K = D_;    N = D_;   break;
        case 3: in = Wo; out = owo;              K = D_;    N = D_;   break;
        case 4: in = W1; out = ow1;              K = D_;    N = DFF_; break;
        case 5: in = W2; out = ow2;              K = DFF_;  N = D_;   break;
        default:in = Wp; out = owp;              K = D_+P_; N = P_;   break;
    }
    const int n0 = blockIdx.x*32, k0 = blockIdx.y*32;
    if (n0 >= N || k0 >= K) return;
    __shared__ float tile[32][33];
    const int tx = threadIdx.x, ty = threadIdx.y;   // 32x8
    #pragma unroll
    for (int j = 0; j < 32; j += 8)
        tile[ty+j][tx] = in[(size_t)(k0+ty+j)*N + n0+tx];
    __syncthreads();
    #pragma unroll
    for (int j = 0; j < 32; j += 8)
        out[(size_t)(n0+ty+j)*K + k0+tx] = __float2half_rn(tile[tx][ty+j]);
}

__global__ void hconv_kernel(const float* __restrict__ in, __half* __restrict__ out, int n) {
    int i = (blockIdx.x * 256 + threadIdx.x) * 4;
    if (i < n) {
        float4 v = *(const float4*)(in + i);
        __half2* o2 = (__half2*)(out + i);
        o2[0] = __floats2half2_rn(v.x, v.y);
        o2[1] = __floats2half2_rn(v.z, v.w);
    }
}

__global__ void bcat_kernel(const float* __restrict__ bq, const float* __restrict__ bk,
                            const float* __restrict__ bv, float* __restrict__ out) {
    int i = blockIdx.x*256 + threadIdx.x;
    out[i] = (i < D_) ? bq[i] : (i < 2*D_) ? bk[i - D_] : bv[i - 2*D_];
}

// V transpose: qkvV[b*S+s][stride 3072] half -> vt[((b*H+h)*64+d)][S] half
__global__ void vtrans_kernel(const __half* __restrict__ v, __half* __restrict__ vt) {
    __shared__ __half tile[32][33];
    const int d0 = blockIdx.x*32, s0 = blockIdx.y*32, b = blockIdx.z;
    const int tx = threadIdx.x, ty = threadIdx.y;   // 32x8
    #pragma unroll
    for (int j = 0; j < 32; j += 8)
        tile[ty+j][tx] = v[(size_t)(b*S_ + s0+ty+j)*(3*D_) + d0+tx];
    __syncthreads();
    const int h = d0 >> 6, dr = d0 & 63;
    #pragma unroll
    for (int j = 0; j < 32; j += 8)
        vt[(size_t)((b*H_ + h)*64 + dr+ty+j)*S_ + s0+tx] = tile[tx][ty+j];
}

// ---------------- LayerNorm: optional exact f32 + half output ----------------
__global__ void ln_kernel(const float* __restrict__ in,
                          const float* __restrict__ alpha,
                          const float* __restrict__ beta,
                          float* __restrict__ out,      // exact (nullable)
                          __half* __restrict__ outh) {  // half
    const int row = blockIdx.x;
    const int t = threadIdx.x;            // 256 threads, 4 elems each
    const float* x = in + (size_t)row * D_;
    float v[4];
    float s = 0.f;
    #pragma unroll
    for (int i = 0; i < 4; i++) { v[i] = x[t + 256*i]; s += v[i]; }

    __shared__ float red[8];
    #pragma unroll
    for (int o = 16; o > 0; o >>= 1) s += __shfl_xor_sync(0xffffffffu, s, o);
    if ((t & 31) == 0) red[t >> 5] = s;
    __syncthreads();
    float tot = 0.f;
    #pragma unroll
    for (int i = 0; i < 8; i++) tot += red[i];
    const float mu = tot * (1.0f / D_);

    float ss = 0.f;
    #pragma unroll
    for (int i = 0; i < 4; i++) { float d = v[i] - mu; ss += d * d; }
    __syncthreads();
    #pragma unroll
    for (int o = 16; o > 0; o >>= 1) ss += __shfl_xor_sync(0xffffffffu, ss, o);
    if ((t & 31) == 0) red[t >> 5] = ss;
    __syncthreads();
    float sst = 0.f;
    #pragma unroll
    for (int i = 0; i < 8; i++) sst += red[i];

    const float stdv = sqrtf(fmaxf(sst, 0.f) * (1.0f / (D_ - 1)));
    const float inv = 1.0f / (stdv + EPS_);
    float*  o  = out  ? out  + (size_t)row * D_ : nullptr;
    __half* oh = outh + (size_t)row * D_;
    #pragma unroll
    for (int i = 0; i < 4; i++) {
        int c = t + 256*i;
        const float y = alpha[c] * (v[i] - mu) * inv + beta[c];
        oh[c] = __float2half_rn(y);
        if (o) o[c] = y;
    }
}

// ---------------- fp16 mma GEMM: 128x256 CTA tile, 64-K chunks, 4-stage cp.async ----------------
// A[M][K1] + optional A2[M][K2] (concatenated along K); Bt[N][K1+K2] k-contiguous.
// 256 threads, 8 warps in 2(m) x 4(n), warp tile 64x64. Single barrier per k-iter
// (safe: 4 stages >= issue-distance 2 + 2).
#define SWW 36                    // smem row stride in words (72 halves, 144B)
#define ASTG (128*72)             // A stage halves
#define BSTG (256*72)             // B stage halves
#define STGH (ASTG + BSTG)        // halves per stage (27648)
#define GEMM_SMEM (4*STGH*2)      // 221184 bytes

template<bool RELU, bool HASBIAS, bool HASRES>
__global__ __launch_bounds__(256, 1)
void hgemm(const __half* __restrict__ A, int K1,
           const __half* __restrict__ A2, int K2,
           const __half* __restrict__ Bt,
           const float* __restrict__ bias, const float* __restrict__ res,
           float* __restrict__ C, __half* __restrict__ Ch,
           int M, int N) {
    extern __shared__ __half hsm[];
    const uint32_t sb = smem_u32(hsm);
    const int t = threadIdx.x;
    const int w = t >> 5, lane = t & 31;
    const int wm = w >> 2, wn = w & 3;       // warp grid 2 (m) x 4 (n), warp tile 64x64
    const int g = lane >> 2, tg = lane & 3;
    const int bx = blockIdx.x, by = blockIdx.y;

    // ldmatrix lane addressing
    const int quad = lane >> 3, lrow = lane & 7;
    const uint32_t frow = (quad & 1)*8 + lrow;
    const uint32_t fcol = (quad >> 1)*8;

    const int KB = K1 + K2;
    const int KT = KB >> 6, K1T = K1 >> 6;
    const __half* Ab  = A  + (size_t)by * 128 * K1;
    const __half* A2b = A2 ? A2 + (size_t)by * 128 * K2 : Ab;
    const __half* Bb  = Bt + (size_t)bx * 256 * KB;

    // prologue: stages 0,1 (tiles 0,1)
    #pragma unroll
    for (int s = 0; s < 2; s++) {
        const uint32_t as = sb + (s*STGH)*2;
        const uint32_t bs = as + ASTG*2;
        #pragma unroll
        for (int j = 0; j < 4; j++) {        // A: 1024 chunks
            const int c = t + 256*j;
            const int row = c >> 3, c8 = c & 7;
            const __half* asrc = (s < K1T) ? Ab + (size_t)row*K1 + s*64 + c8*8
                                           : A2b + (size_t)row*K2 + (s - K1T)*64 + c8*8;
            cp16(as + (row*72 + c8*8)*2, asrc);
        }
        #pragma unroll
        for (int j = 0; j < 8; j++) {        // B: 2048 chunks
            const int c = t + 256*j;
            const int row = c >> 3, c8 = c & 7;
            cp16(bs + (row*72 + c8*8)*2, Bb + (size_t)row*KB + s*64 + c8*8);
        }
        cp_commit();
    }

    float acc[4][8][4];
    #pragma unroll
    for (int mi = 0; mi < 4; mi++)
        #pragma unroll
        for (int ni = 0; ni < 8; ni++)
            #pragma unroll
            for (int r = 0; r < 4; r++) acc[mi][ni][r] = 0.f;

    for (int kt = 0; kt < KT; kt++) {
        // issue stage kt+2 (writes stage read at iter kt-2; all warps past barrier kt-1
        // have finished compute kt-2, so single-barrier is safe with 4 stages)
        if (kt + 2 < KT) {
            const int kc = kt + 2;
            const int s = kc & 3;
            const uint32_t as = sb + (s*STGH)*2;
            const uint32_t bs = as + ASTG*2;
            #pragma unroll
            for (int j = 0; j < 4; j++) {
                const int c = t + 256*j;
                const int row = c >> 3, c8 = c & 7;
                const __half* asrc = (kc < K1T) ? Ab + (size_t)row*K1 + kc*64 + c8*8
                                                : A2b + (size_t)row*K2 + (kc - K1T)*64 + c8*8;
                cp16(as + (row*72 + c8*8)*2, asrc);
            }
            #pragma unroll
            for (int j = 0; j < 8; j++) {
                const int c = t + 256*j;
                const int row = c >> 3, c8 = c & 7;
                cp16(bs + (row*72 + c8*8)*2, Bb + (size_t)row*KB + kc*64 + c8*8);
            }
        }
        cp_commit();
        cp_wait<2>();          // tile kt complete
        __syncthreads();

        const int cs = kt & 3;
        const uint32_t asb = sb + (cs*STGH)*2;
        const uint32_t bsb = asb + ASTG*2;
        const uint32_t aoff = asb + ((wm*64 + frow)*72 + fcol)*2;
        const uint32_t boff = bsb + ((wn*64 + frow)*72 + fcol)*2;
        #pragma unroll
        for (int kk = 0; kk < 4; kk++) {
            uint32_t af[4][4];
            #pragma unroll
            for (int mi = 0; mi < 4; mi++)
                ldsm4(af[mi], aoff + (mi*16*72 + kk*16)*2);
            uint32_t bqd[4][4];
            #pragma unroll
            for (int j = 0; j < 4; j++)
                ldsm4(bqd[j], boff + (j*16*72 + kk*16)*2);
            #pragma unroll
            for (int mi = 0; mi < 4; mi++) {
                #pragma unroll
                for (int j = 0; j < 4; j++) {
                    uint32_t bf0[2] = { bqd[j][0], bqd[j][2] };
                    uint32_t bf1[2] = { bqd[j][1], bqd[j][3] };
                    mma_f16(acc[mi][2*j],     af[mi], bf0);
                    mma_f16(acc[mi][2*j + 1], af[mi], bf1);
                }
            }
        }
    }

    // epilogue
    #pragma unroll
    for (int mi = 0; mi < 4; mi++) {
        #pragma unroll
        for (int ni = 0; ni < 8; ni++) {
            const size_t row0 = (size_t)by*128 + wm*64 + mi*16 + g;
            const size_t row1 = row0 + 8;
            const int col = bx*256 + wn*64 + ni*8 + 2*tg;
            float v0 = acc[mi][ni][0], v1 = acc[mi][ni][1];
            float v2 = acc[mi][ni][2], v3 = acc[mi][ni][3];
            if (HASBIAS) {
                const float bb0 = bias[col], bb1 = bias[col+1];
                v0 += bb0; v1 += bb1; v2 += bb0; v3 += bb1;
            }
            if (HASRES) {
                v0 += res[row0*N + col]; v1 += res[row0*N + col + 1];
                v2 += res[row1*N + col]; v3 += res[row1*N + col + 1];
            }
            if (RELU) {
                v0 = fmaxf(v0, 0.f); v1 = fmaxf(v1, 0.f);
                v2 = fmaxf(v2, 0.f); v3 = fmaxf(v3, 0.f);
            }
            if (Ch) {
                *(__half2*)&Ch[row0*N + col] = __floats2half2_rn(v0, v1);
                *(__half2*)&Ch[row1*N + col] = __floats2half2_rn(v2, v3);
            }
            if (C) {
                *(float2*)&C[row0*N + col] = make_float2(v0, v1);
                *(float2*)&C[row1*N + col] = make_float2(v2, v3);
            }
        }
    }
}

// ---------------- fp16 flash attention: 256 threads (8 warps), 128 queries/CTA ----------------
// 3-stage cp.async K/V ring (single barrier/iter); P reused directly from S registers
// as the A operand of P·V (C-fragment == A-fragment layout).
#define ATTN_SMEM ((128 + 6*64) * 72 * 2)   // 73728 B
#define SCL2 0.18033688011112042f           // 0.125 * log2(e)

__global__ __launch_bounds__(256, 2)
void attn_kernel(const __half* __restrict__ QKV, const __half* __restrict__ Vt,
                 __half* __restrict__ O) {
    extern __shared__ __half smh[];
    __half* Ps = smh;                     // [128][72] (Q staging only)
    __half* Kb = Ps + 128*72;             // [3][64][72]
    __half* Vb = Kb + 3*64*72;            // [3][64][72]

    const int qt = blockIdx.x, h = blockIdx.y, b = blockIdx.z;
    const int t = threadIdx.x;
    const int wq = t >> 5, lane = t & 31;
    const int g = lane >> 2, tg = lane & 3;

    const int quad = lane >> 3, lrow = lane & 7;
    const uint32_t frow = (quad & 1)*8 + lrow;
    const uint32_t fcol = (quad >> 1)*8;

    const uint32_t Ps_u = smem_u32(Ps);
    const uint32_t Kb_u = smem_u32(Kb);
    const uint32_t Vb_u = smem_u32(Vb);

    const __half* Qp = QKV + (size_t)h*DH_;                    // stride 3*D_
    const __half* Kp = QKV + D_ + (size_t)h*DH_;
    const __half* Vrow = Vt + (size_t)((b*H_ + h)*64) * S_;

    // ---- stage Q tile [128][64] into Ps ----
    #pragma unroll
    for (int i = 0; i < 4; i++) {
        const int c = t + 256*i;        // 1024 chunks of 16B
        const int row = c >> 3, c8 = c & 7;
        *(uint4*)(Ps + row*72 + c8*8) =
            *(const uint4*)(Qp + ((size_t)(b*S_ + qt*128 + row))*(3*D_) + c8*8);
    }

    // ---- issue cp.async for K/V tile 0 (buffer 0) ----
    {
        #pragma unroll
        for (int i = 0; i < 2; i++) {
            const int c = t + 256*i;     // 512 chunks each
            const int row = c >> 3, c8 = c & 7;
            cp16(Kb_u + (row*72 + c8*8)*2,
                 Kp + ((size_t)(b*S_ + row))*(3*D_) + c8*8);
            cp16(Vb_u + (row*72 + c8*8)*2,
                 Vrow + (size_t)row*S_ + c8*8);
        }
        cp_commit();
    }
    __syncthreads();

    // ---- preload Q fragments ----
    uint32_t aQ[4][4];
    {
        const uint32_t qoff = Ps_u + ((wq*16 + frow)*72 + fcol)*2;
        #pragma unroll
        for (int kk = 0; kk < 4; kk++)
            ldsm4(aQ[kk], qoff + kk*16*2);
    }

    float m[2], l[2], o[8][4];
    m[0] = m[1] = -1e30f; l[0] = l[1] = 0.f;
    #pragma unroll
    for (int ni = 0; ni < 8; ni++)
        #pragma unroll
        for (int r = 0; r < 4; r++) o[ni][r] = 0.f;

    const uint32_t kfoff = (frow*72 + fcol)*2;
    const int NT = S_/64;

    for (int kt = 0; kt < NT; kt++) {
        // issue tile kt+1 into buf (kt+1)%3 (last read at iter kt-2; safe w/ 1 barrier)
        if (kt + 1 < NT) {
            const int nb = (kt+1) % 3;
            const uint32_t kb = Kb_u + (nb*64*72)*2;
            const uint32_t vb = Vb_u + (nb*64*72)*2;
            #pragma unroll
            for (int i = 0; i < 2; i++) {
                const int c = t + 256*i;
                const int row = c >> 3, c8 = c & 7;
                cp16(kb + (row*72 + c8*8)*2,
                     Kp + ((size_t)(b*S_ + (kt+1)*64 + row))*(3*D_) + c8*8);
                cp16(vb + (row*72 + c8*8)*2,
                     Vrow + (size_t)row*S_ + (kt+1)*64 + c8*8);
            }
        }
        cp_commit();
        cp_wait<1>();      // tile kt landed
        __syncthreads();

        const int cb = kt % 3;
        const uint32_t Ks_u = Kb_u + (cb*64*72)*2;
        const uint32_t Vs_u = Vb_u + (cb*64*72)*2;

        // ---- S = Q K^T (raw, unscaled) ----
        float acc[8][4];
        #pragma unroll
        for (int ni = 0; ni < 8; ni++)
            #pragma unroll
            for (int r = 0; r < 4; r++) acc[ni][r] = 0.f;

        #pragma unroll
        for (int kk = 0; kk < 4; kk++) {
            #pragma unroll
            for (int j = 0; j < 4; j++) {
                uint32_t kq[4];
                ldsm4(kq, Ks_u + kfoff + (j*16*72 + kk*16)*2);
                uint32_t bf0[2] = { kq[0], kq[2] };
                uint32_t bf1[2] = { kq[1], kq[3] };
                mma_f16(acc[2*j],     aQ[kk], bf0);
                mma_f16(acc[2*j + 1], aQ[kk], bf1);
            }
        }

        // ---- online softmax in base-2 domain ----
        float tm0 = -1e30f, tm1 = -1e30f;
        #pragma unroll
        for (int ni = 0; ni < 8; ni++) {
            tm0 = fmaxf(tm0, fmaxf(acc[ni][0], acc[ni][1]));
            tm1 = fmaxf(tm1, fmaxf(acc[ni][2], acc[ni][3]));
        }
        #pragma unroll
        for (int off = 1; off < 4; off <<= 1) {
            tm0 = fmaxf(tm0, __shfl_xor_sync(0xffffffffu, tm0, off));
            tm1 = fmaxf(tm1, __shfl_xor_sync(0xffffffffu, tm1, off));
        }
        tm0 *= SCL2; tm1 *= SCL2;      // log2 domain
        const float mn0 = fmaxf(m[0], tm0);
        const float mn1 = fmaxf(m[1], tm1);
        const float corr0 = exp2f(m[0] - mn0);
        const float corr1 = exp2f(m[1] - mn1);
        float ts0 = 0.f, ts1 = 0.f;
        #pragma unroll
        for (int ni = 0; ni < 8; ni++) {
            acc[ni][0] = exp2f(fmaf(acc[ni][0], SCL2, -mn0));
            acc[ni][1] = exp2f(fmaf(acc[ni][1], SCL2, -mn0));
            acc[ni][2] = exp2f(fmaf(acc[ni][2], SCL2, -mn1));
            acc[ni][3] = exp2f(fmaf(acc[ni][3], SCL2, -mn1));
            ts0 += acc[ni][0] + acc[ni][1];
            ts1 += acc[ni][2] + acc[ni][3];
        }
        #pragma unroll
        for (int off = 1; off < 4; off <<= 1) {
            ts0 += __shfl_xor_sync(0xffffffffu, ts0, off);
            ts1 += __shfl_xor_sync(0xffffffffu, ts1, off);
        }
        l[0] = l[0]*corr0 + ts0;  m[0] = mn0;
        l[1] = l[1]*corr1 + ts1;  m[1] = mn1;
        #pragma unroll
        for (int ni = 0; ni < 8; ni++) {
            o[ni][0] *= corr0; o[ni][1] *= corr0;
            o[ni][2] *= corr1; o[ni][3] *= corr1;
        }

        // ---- O += P V : P taken directly from S registers (C-frag == A-frag) ----
        #pragma unroll
        for (int kk = 0; kk < 4; kk++) {
            uint32_t aP[4];
            aP[0] = f2h2(acc[2*kk    ][0], acc[2*kk    ][1]);   // row g,   keys 2tg..2tg+1
            aP[1] = f2h2(acc[2*kk    ][2], acc[2*kk    ][3]);   // row g+8, keys 2tg..2tg+1
            aP[2] = f2h2(acc[2*kk + 1][0], acc[2*kk + 1][1]);   // row g,   keys 8+2tg..
            aP[3] = f2h2(acc[2*kk + 1][2], acc[2*kk + 1][3]);   // row g+8, keys 8+2tg..
            #pragma unroll
            for (int j = 0; j < 4; j++) {
                uint32_t vq[4];
                ldsm4(vq, Vs_u + kfoff + (j*16*72 + kk*16)*2);
                uint32_t bf0[2] = { vq[0], vq[2] };
                uint32_t bf1[2] = { vq[1], vq[3] };
                mma_f16(o[2*j],     aP, bf0);
                mma_f16(o[2*j + 1], aP, bf1);
            }
        }
    }

    // ---- epilogue: O /= l, write half ctx ----
    const float inv0 = 1.0f / l[0];
    const float inv1 = 1.0f / l[1];
    const size_t row0 = (size_t)(b*S_ + qt*128 + wq*16 + g);
    const size_t row1 = row0 + 8;
    #pragma unroll
    for (int ni = 0; ni < 8; ni++) {
        const int col = ni*8 + 2*tg;
        *(__half2*)&O[row0*D_ + h*DH_ + col] = __floats2half2_rn(o[ni][0]*inv0, o[ni][1]*inv0);
        *(__half2*)&O[row1*D_ + h*DH_ + col] = __floats2half2_rn(o[ni][2]*inv1, o[ni][3]*inv1);
    }
}

// ---------------- host launcher ----------------
extern "C" void kernel_launch(void* const* d_in, const int* in_sizes, int n_in,
                              void* d_out, int out_size) {
    const float* fx  = (const float*)d_in[0];
    const float* px  = (const float*)d_in[1];
    const float* Wq  = (const float*)d_in[2];
    const float* bq  = (const float*)d_in[3];
    const float* Wk  = (const float*)d_in[4];
    const float* bk  = (const float*)d_in[5];
    const float* Wv  = (const float*)d_in[6];
    const float* bv  = (const float*)d_in[7];
    const float* Wo  = (const float*)d_in[8];
    const float* bo  = (const float*)d_in[9];
    const float* a1  = (const float*)d_in[10];
    const float* be1 = (const float*)d_in[11];
    const float* a2  = (const float*)d_in[12];
    const float* be2 = (const float*)d_in[13];
    const float* W1  = (const float*)d_in[14];
    const float* b1  = (const float*)d_in[15];
    const float* W2  = (const float*)d_in[16];
    const float* b2  = (const float*)d_in[17];
    const float* Wp  = (const float*)d_in[18];
    const float* bp  = (const float*)d_in[19];

    float* xo = (float*)d_out;                    // x: M_ x D_
    float* po = xo + (size_t)M_ * D_;             // p: M_ x P_

    float  *xn, *bqkv;
    __half *xnr, *qkv, *vt, *ctx, *x2h, *hbh, *xrh, *pxh;
    __half *wqkvT, *woT, *w1T, *w2T, *wpT;
    cudaGetSymbolAddress((void**)&xn,    g_xn);
    cudaGetSymbolAddress((void**)&xnr,   g_xnr);
    cudaGetSymbolAddress((void**)&qkv,   g_qkv);
    cudaGetSymbolAddress((void**)&vt,    g_vt);
    cudaGetSymbolAddress((void**)&ctx,   g_ctx);
    cudaGetSymbolAddress((void**)&x2h,   g_x2);
    cudaGetSymbolAddress((void**)&hbh,   g_hb);
    cudaGetSymbolAddress((void**)&xrh,   g_xr);
    cudaGetSymbolAddress((void**)&pxh,   g_pxh);
    cudaGetSymbolAddress((void**)&wqkvT, g_wqkvT);
    cudaGetSymbolAddress((void**)&woT,   g_woT);
    cudaGetSymbolAddress((void**)&w1T,   g_w1T);
    cudaGetSymbolAddress((void**)&w2T,   g_w2T);
    cudaGetSymbolAddress((void**)&wpT,   g_wpT);
    cudaGetSymbolAddress((void**)&bqkv,  g_bqkv);

    cudaFuncSetAttribute(attn_kernel, cudaFuncAttributeMaxDynamicSharedMemorySize, ATTN_SMEM);
    cudaFuncSetAttribute(hgemm<false,true,false>, cudaFuncAttributeMaxDynamicSharedMemorySize, GEMM_SMEM);
    cudaFuncSetAttribute(hgemm<false,true,true>,  cudaFuncAttributeMaxDynamicSharedMemorySize, GEMM_SMEM);
    cudaFuncSetAttribute(hgemm<true,true,false>,  cudaFuncAttributeMaxDynamicSharedMemorySize, GEMM_SMEM);

    // 0. weight transposes + conversions (one fused launch for all 7 weights)
    dim3 tb(32, 8);
    wtrans_all_kernel<<<dim3(32, 40, 7), tb>>>(Wq, Wk, Wv, Wo, W1, W2, Wp,
                                               wqkvT, woT, w1T, w2T, wpT);
    bcat_kernel<<<(3*D_)/256, 256>>>(bq, bk, bv, bqkv);
    hconv_kernel<<<(M_*P_)/1024, 256>>>(px, pxh, M_*P_);

    // 1. xn = LN1(feature_x): exact -> xn, half -> xnr
    ln_kernel<<<M_, 256>>>(fx, a1, be1, xn, xnr);

    // 2. fused QKV GEMM: [M][3072]
    hgemm<false,true,false><<<dim3(3*D_/256, M_/128), 256, GEMM_SMEM>>>(
        xnr, D_, nullptr, 0, wqkvT, bqkv, nullptr, nullptr, qkv, M_, 3*D_);

    // 2b. transpose V slice for PV mma
    vtrans_kernel<<<dim3(D_/32, S_/32, B_), tb>>>(qkv + 2*D_, vt);

    // 3. attention -> ctx (half)
    attn_kernel<<<dim3(S_/128, H_, B_), 256, ATTN_SMEM>>>(qkv, vt, ctx);

    // 4. x = xn + ctx@Wo + bo (f32 -> d_out)
    dim3 gD(D_/256, M_/128);
    hgemm<false,true,true><<<gD, 256, GEMM_SMEM>>>(
        ctx, D_, nullptr, 0, woT, bo, xn, xo, nullptr, M_, D_);

    // 5. x2 = LN2(x) (half only)
    ln_kernel<<<M_, 256>>>(xo, a2, be2, nullptr, x2h);

    // 6. h = relu(x2@W1+b1) (half); x = x + h@W2 + b2 (f32 -> d_out, half -> xrh)
    hgemm<true,true,false><<<dim3(DFF_/256, M_/128), 256, GEMM_SMEM>>>(
        x2h, D_, nullptr, 0, w1T, b1, nullptr, nullptr, hbh, M_, DFF_);
    hgemm<false,true,true><<<gD, 256, GEMM_SMEM>>>(
        hbh, DFF_, nullptr, 0, w2T, b2, xo, xo, xrh, M_, D_);

    // 7. p = [x, param_x] @ Wp + bp (single dual-A GEMM, K = 1024 + 256)
    hgemm<false,true,false><<<dim3(P_/256, M_/128), 256, GEMM_SMEM>>>(
        xrh, D_, pxh, P_, wpT, bp, nullptr, po, nullptr, M_, P_);
}

// round 12
// speedup vs baseline: 1.0866x; 1.0866x over previous
#include <cuda_runtime.h>
#include <cuda_fp16.h>
#include <cstdint>

// ---------------- problem constants ----------------
#define B_  4
#define S_  2048
#define D_  1024
#define P_  256
#define H_  16
#define DH_ 64
#define DFF_ 512
#define M_  (B_*S_)           // 8192 rows
#define EPS_ 1e-6f

// ---------------- scratch (static device globals; no allocation) ----------------
__device__ float  g_xn [M_*D_];          // exact LN1 output (residual)
__device__ __half g_xnr[M_*D_];          // half LN1 output (GEMM A)
__device__ __half g_qkv[M_*3*D_];        // fused QKV output [M][3072]
__device__ __half g_vt [M_*D_];          // V transposed: [(b*H+h)*64+d][S]
__device__ __half g_ctx[M_*D_];
__device__ __half g_x2 [M_*D_];
__device__ __half g_hb [M_*DFF_];
__device__ __half g_xr [M_*D_];          // half copy of final x (Wp input)
__device__ __half g_pxh[M_*P_];
__device__ __half g_wqkvT[3*D_*D_];      // [3072][1024]
__device__ __half g_woT[D_*D_];
__device__ __half g_w1T[D_*DFF_];
__device__ __half g_w2T[DFF_*D_];
__device__ __half g_wpT[P_*(D_+P_)];     // [256][1280]
__device__ float  g_bqkv[3*D_];

// ---------------- ptx helpers ----------------
__device__ __forceinline__ void mma_f16(float c[4], const uint32_t a[4], const uint32_t b[2]) {
    asm volatile(
        "mma.sync.aligned.m16n8k16.row.col.f32.f16.f16.f32 "
        "{%0,%1,%2,%3}, {%4,%5,%6,%7}, {%8,%9}, {%0,%1,%2,%3};\n"
        : "+f"(c[0]), "+f"(c[1]), "+f"(c[2]), "+f"(c[3])
        : "r"(a[0]), "r"(a[1]), "r"(a[2]), "r"(a[3]), "r"(b[0]), "r"(b[1]));
}

__device__ __forceinline__ void ldsm4(uint32_t r[4], uint32_t addr) {
    asm volatile("ldmatrix.sync.aligned.m8n8.x4.shared.b16 {%0,%1,%2,%3}, [%4];"
        : "=r"(r[0]), "=r"(r[1]), "=r"(r[2]), "=r"(r[3]) : "r"(addr));
}

__device__ __forceinline__ uint32_t smem_u32(const void* p) {
    uint32_t a;
    asm("{ .reg .u64 t; cvta.to.shared.u64 t, %1; cvt.u32.u64 %0, t; }" : "=r"(a) : "l"(p));
    return a;
}

__device__ __forceinline__ void cp16(uint32_t dst, const void* src) {
    asm volatile("cp.async.ca.shared.global [%0], [%1], 16;" :: "r"(dst), "l"(src));
}
__device__ __forceinline__ void cp_commit() {
    asm volatile("cp.async.commit_group;" ::: "memory");
}
template<int N_>
__device__ __forceinline__ void cp_wait() {
    asm volatile("cp.async.wait_group %0;" :: "n"(N_) : "memory");
}

__device__ __forceinline__ uint32_t f2h2(float a, float b) {
    __half2 h = __floats2half2_rn(a, b);
    return *(uint32_t*)&h;
}

// ---------------- prep kernels ----------------
// Unified transpose+convert for all 7 weights: in[K][N] f32 -> out[N][K] half.
// z: 0 Wq, 1 Wk, 2 Wv (-> wqkvT slices), 3 Wo, 4 W1, 5 W2, 6 Wp.
__global__ void wtrans_all_kernel(const float* __restrict__ Wq, const float* __restrict__ Wk,
                                  const float* __restrict__ Wv, const float* __restrict__ Wo,
                                  const float* __restrict__ W1, const float* __restrict__ W2,
                                  const float* __restrict__ Wp,
                                  __half* __restrict__ oqkv, __half* __restrict__ owo,
                                  __half* __restrict__ ow1, __half* __restrict__ ow2,
                                  __half* __restrict__ owp) {
    const int z = blockIdx.z;
    const float* in; __half* out; int K, N;
    switch (z) {
        case 0: in = Wq; out = oqkv;             K = D_;    N = D_;   break;
        case 1: in = Wk; out = oqkv + D_*D_;     K = D_;    N = D_;   break;
        case 2: in = Wv; out = oqkv + 2*D_*D_;   K = D_;    N = D_;   break;
        case 3: in = Wo; out = owo;              K = D_;    N = D_;   break;
        case 4: in = W1; out = ow1;              K = D_;    N = DFF_; break;
        case 5: in = W2; out = ow2;              K = DFF_;  N = D_;   break;
        default:in = Wp; out = owp;              K = D_+P_; N = P_;   break;
    }
    const int n0 = blockIdx.x*32, k0 = blockIdx.y*32;
    if (n0 >= N || k0 >= K) return;
    __shared__ float tile[32][33];
    const int tx = threadIdx.x, ty = threadIdx.y;   // 32x8
    #pragma unroll
    for (int j = 0; j < 32; j += 8)
        tile[ty+j][tx] = in[(size_t)(k0+ty+j)*N + n0+tx];
    __syncthreads();
    #pragma unroll
    for (int j = 0; j < 32; j += 8)
        out[(size_t)(n0+ty+j)*K + k0+tx] = __float2half_rn(tile[tx][ty+j]);
}

__global__ void hconv_kernel(const float* __restrict__ in, __half* __restrict__ out, int n) {
    int i = (blockIdx.x * 256 + threadIdx.x) * 4;
    if (i < n) {
        float4 v = *(const float4*)(in + i);
        __half2* o2 = (__half2*)(out + i);
        o2[0] = __floats2half2_rn(v.x, v.y);
        o2[1] = __floats2half2_rn(v.z, v.w);
    }
}

__global__ void bcat_kernel(const float* __restrict__ bq, const float* __restrict__ bk,
                            const float* __restrict__ bv, float* __restrict__ out) {
    int i = blockIdx.x*256 + threadIdx.x;
    out[i] = (i < D_) ? bq[i] : (i < 2*D_) ? bk[i - D_] : bv[i - 2*D_];
}

// V transpose: qkvV[b*S+s][stride 3072] half -> vt[((b*H+h)*64+d)][S] half
__global__ void vtrans_kernel(const __half* __restrict__ v, __half* __restrict__ vt) {
    __shared__ __half tile[32][33];
    const int d0 = blockIdx.x*32, s0 = blockIdx.y*32, b = blockIdx.z;
    const int tx = threadIdx.x, ty = threadIdx.y;   // 32x8
    #pragma unroll
    for (int j = 0; j < 32; j += 8)
        tile[ty+j][tx] = v[(size_t)(b*S_ + s0+ty+j)*(3*D_) + d0+tx];
    __syncthreads();
    const int h = d0 >> 6, dr = d0 & 63;
    #pragma unroll
    for (int j = 0; j < 32; j += 8)
        vt[(size_t)((b*H_ + h)*64 + dr+ty+j)*S_ + s0+tx] = tile[tx][ty+j];
}

// ---------------- LayerNorm: optional exact f32 + half output ----------------
__global__ void ln_kernel(const float* __restrict__ in,
                          const float* __restrict__ alpha,
                          const float* __restrict__ beta,
                          float* __restrict__ out,      // exact (nullable)
                          __half* __restrict__ outh) {  // half
    const int row = blockIdx.x;
    const int t = threadIdx.x;            // 256 threads, 4 elems each
    const float* x = in + (size_t)row * D_;
    float v[4];
    float s = 0.f;
    #pragma unroll
    for (int i = 0; i < 4; i++) { v[i] = x[t + 256*i]; s += v[i]; }

    __shared__ float red[8];
    #pragma unroll
    for (int o = 16; o > 0; o >>= 1) s += __shfl_xor_sync(0xffffffffu, s, o);
    if ((t & 31) == 0) red[t >> 5] = s;
    __syncthreads();
    float tot = 0.f;
    #pragma unroll
    for (int i = 0; i < 8; i++) tot += red[i];
    const float mu = tot * (1.0f / D_);

    float ss = 0.f;
    #pragma unroll
    for (int i = 0; i < 4; i++) { float d = v[i] - mu; ss += d * d; }
    __syncthreads();
    #pragma unroll
    for (int o = 16; o > 0; o >>= 1) ss += __shfl_xor_sync(0xffffffffu, ss, o);
    if ((t & 31) == 0) red[t >> 5] = ss;
    __syncthreads();
    float sst = 0.f;
    #pragma unroll
    for (int i = 0; i < 8; i++) sst += red[i];

    const float stdv = sqrtf(fmaxf(sst, 0.f) * (1.0f / (D_ - 1)));
    const float inv = 1.0f / (stdv + EPS_);
    float*  o  = out  ? out  + (size_t)row * D_ : nullptr;
    __half* oh = outh + (size_t)row * D_;
    #pragma unroll
    for (int i = 0; i < 4; i++) {
        int c = t + 256*i;
        const float y = alpha[c] * (v[i] - mu) * inv + beta[c];
        oh[c] = __float2half_rn(y);
        if (o) o[c] = y;
    }
}

// ---------------- fp16 mma GEMM: 128x256 CTA tile, 64-K chunks, 3-stage cp.async ----------------
// (identical to R10's kernel)
#define SWW 36                    // smem row stride in words (72 halves, 144B)
#define ASTG (128*72)             // A stage halves
#define BSTG (256*72)             // B stage halves
#define STGH (ASTG + BSTG)        // halves per stage (27648)
#define GEMM_SMEM (3*STGH*2)      // 165888 bytes

template<bool RELU, bool HASBIAS, bool HASRES>
__global__ __launch_bounds__(256, 1)
void hgemm(const __half* __restrict__ A, int K1,
           const __half* __restrict__ A2, int K2,
           const __half* __restrict__ Bt,
           const float* __restrict__ bias, const float* __restrict__ res,
           float* __restrict__ C, __half* __restrict__ Ch,
           int M, int N) {
    extern __shared__ __half hsm[];
    const uint32_t sb = smem_u32(hsm);
    const int t = threadIdx.x;
    const int w = t >> 5, lane = t & 31;
    const int wm = w >> 2, wn = w & 3;       // warp grid 2 (m) x 4 (n), warp tile 64x64
    const int g = lane >> 2, tg = lane & 3;
    const int bx = blockIdx.x, by = blockIdx.y;

    // ldmatrix lane addressing
    const int quad = lane >> 3, lrow = lane & 7;
    const uint32_t frow = (quad & 1)*8 + lrow;
    const uint32_t fcol = (quad >> 1)*8;

    const int KB = K1 + K2;
    const int KT = KB >> 6, K1T = K1 >> 6;
    const __half* Ab  = A  + (size_t)by * 128 * K1;
    const __half* A2b = A2 ? A2 + (size_t)by * 128 * K2 : Ab;
    const __half* Bb  = Bt + (size_t)bx * 256 * KB;

    // prologue: stages 0,1
    #pragma unroll
    for (int s = 0; s < 2; s++) {
        const uint32_t as = sb + (s*STGH)*2;
        const uint32_t bs = as + ASTG*2;
        #pragma unroll
        for (int j = 0; j < 4; j++) {        // A: 1024 chunks
            const int c = t + 256*j;
            const int row = c >> 3, c8 = c & 7;
            const __half* asrc = (s < K1T) ? Ab + (size_t)row*K1 + s*64 + c8*8
                                           : A2b + (size_t)row*K2 + (s - K1T)*64 + c8*8;
            cp16(as + (row*72 + c8*8)*2, asrc);
        }
        #pragma unroll
        for (int j = 0; j < 8; j++) {        // B: 2048 chunks
            const int c = t + 256*j;
            const int row = c >> 3, c8 = c & 7;
            cp16(bs + (row*72 + c8*8)*2, Bb + (size_t)row*KB + s*64 + c8*8);
        }
        cp_commit();
    }

    float acc[4][8][4];
    #pragma unroll
    for (int mi = 0; mi < 4; mi++)
        #pragma unroll
        for (int ni = 0; ni < 8; ni++)
            #pragma unroll
            for (int r = 0; r < 4; r++) acc[mi][ni][r] = 0.f;

    for (int kt = 0; kt < KT; kt++) {
        // issue stage kt+2 first, then wait only for tile kt
        if (kt + 2 < KT) {
            const int kc = kt + 2;
            const int s = kc % 3;
            const uint32_t as = sb + (s*STGH)*2;
            const uint32_t bs = as + ASTG*2;
            #pragma unroll
            for (int j = 0; j < 4; j++) {
                const int c = t + 256*j;
                const int row = c >> 3, c8 = c & 7;
                const __half* asrc = (kc < K1T) ? Ab + (size_t)row*K1 + kc*64 + c8*8
                                                : A2b + (size_t)row*K2 + (kc - K1T)*64 + c8*8;
                cp16(as + (row*72 + c8*8)*2, asrc);
            }
            #pragma unroll
            for (int j = 0; j < 8; j++) {
                const int c = t + 256*j;
                const int row = c >> 3, c8 = c & 7;
                cp16(bs + (row*72 + c8*8)*2, Bb + (size_t)row*KB + kc*64 + c8*8);
            }
        }
        cp_commit();
        cp_wait<2>();          // tile kt complete; kt+1, kt+2 may still be in flight
        __syncthreads();

        const int cs = kt % 3;
        const uint32_t asb = sb + (cs*STGH)*2;
        const uint32_t bsb = asb + ASTG*2;
        const uint32_t aoff = asb + ((wm*64 + frow)*72 + fcol)*2;
        const uint32_t boff = bsb + ((wn*64 + frow)*72 + fcol)*2;
        #pragma unroll
        for (int kk = 0; kk < 4; kk++) {
            uint32_t af[4][4];
            #pragma unroll
            for (int mi = 0; mi < 4; mi++)
                ldsm4(af[mi], aoff + (mi*16*72 + kk*16)*2);
            uint32_t bqd[4][4];
            #pragma unroll
            for (int j = 0; j < 4; j++)
                ldsm4(bqd[j], boff + (j*16*72 + kk*16)*2);
            #pragma unroll
            for (int mi = 0; mi < 4; mi++) {
                #pragma unroll
                for (int j = 0; j < 4; j++) {
                    uint32_t bf0[2] = { bqd[j][0], bqd[j][2] };
                    uint32_t bf1[2] = { bqd[j][1], bqd[j][3] };
                    mma_f16(acc[mi][2*j],     af[mi], bf0);
                    mma_f16(acc[mi][2*j + 1], af[mi], bf1);
                }
            }
        }
        __syncthreads();   // all warps done with stage kt before it is overwritten (kt+3)
    }

    // epilogue
    #pragma unroll
    for (int mi = 0; mi < 4; mi++) {
        #pragma unroll
        for (int ni = 0; ni < 8; ni++) {
            const size_t row0 = (size_t)by*128 + wm*64 + mi*16 + g;
            const size_t row1 = row0 + 8;
            const int col = bx*256 + wn*64 + ni*8 + 2*tg;
            float v0 = acc[mi][ni][0], v1 = acc[mi][ni][1];
            float v2 = acc[mi][ni][2], v3 = acc[mi][ni][3];
            if (HASBIAS) {
                const float bb0 = bias[col], bb1 = bias[col+1];
                v0 += bb0; v1 += bb1; v2 += bb0; v3 += bb1;
            }
            if (HASRES) {
                v0 += res[row0*N + col]; v1 += res[row0*N + col + 1];
                v2 += res[row1*N + col]; v3 += res[row1*N + col + 1];
            }
            if (RELU) {
                v0 = fmaxf(v0, 0.f); v1 = fmaxf(v1, 0.f);
                v2 = fmaxf(v2, 0.f); v3 = fmaxf(v3, 0.f);
            }
            if (Ch) {
                *(__half2*)&Ch[row0*N + col] = __floats2half2_rn(v0, v1);
                *(__half2*)&Ch[row1*N + col] = __floats2half2_rn(v2, v3);
            }
            if (C) {
                *(float2*)&C[row0*N + col] = make_float2(v0, v1);
                *(float2*)&C[row1*N + col] = make_float2(v2, v3);
            }
        }
    }
}

// ---------------- fp16 flash attention: 256 threads (8 warps), 128 queries/CTA ----------------
// R10 structure (double-buffered K/V, two barriers/iter); ONLY change vs R10:
// P is fed to the PV mma directly from the S-accumulator registers (C-frag == A-frag),
// eliminating the P smem round-trip (16 STS + 4 LDSM + syncwarp per tile).
#define ATTN_SMEM ((128 + 4*64) * 72 * 2)   // 55296 B
#define SCL2 0.18033688011112042f           // 0.125 * log2(e)

__global__ __launch_bounds__(256, 2)
void attn_kernel(const __half* __restrict__ QKV, const __half* __restrict__ Vt,
                 __half* __restrict__ O) {
    extern __shared__ __half smh[];
    __half* Ps = smh;                     // [128][72] (Q staging only)
    __half* Kb = Ps + 128*72;             // [2][64][72]
    __half* Vb = Kb + 2*64*72;            // [2][64][72]

    const int qt = blockIdx.x, h = blockIdx.y, b = blockIdx.z;
    const int t = threadIdx.x;
    const int wq = t >> 5, lane = t & 31;
    const int g = lane >> 2, tg = lane & 3;

    const int quad = lane >> 3, lrow = lane & 7;
    const uint32_t frow = (quad & 1)*8 + lrow;
    const uint32_t fcol = (quad >> 1)*8;

    const uint32_t Ps_u = smem_u32(Ps);
    const uint32_t Kb_u = smem_u32(Kb);
    const uint32_t Vb_u = smem_u32(Vb);

    const __half* Qp = QKV + (size_t)h*DH_;                    // stride 3*D_
    const __half* Kp = QKV + D_ + (size_t)h*DH_;
    const __half* Vrow = Vt + (size_t)((b*H_ + h)*64) * S_;

    // ---- stage Q tile [128][64] into Ps ----
    #pragma unroll
    for (int i = 0; i < 4; i++) {
        const int c = t + 256*i;        // 1024 chunks of 16B
        const int row = c >> 3, c8 = c & 7;
        *(uint4*)(Ps + row*72 + c8*8) =
            *(const uint4*)(Qp + ((size_t)(b*S_ + qt*128 + row))*(3*D_) + c8*8);
    }

    // ---- issue cp.async for K/V tile 0 (buffer 0) ----
    {
        #pragma unroll
        for (int i = 0; i < 2; i++) {
            const int c = t + 256*i;     // 512 chunks each
            const int row = c >> 3, c8 = c & 7;
            cp16(Kb_u + (row*72 + c8*8)*2,
                 Kp + ((size_t)(b*S_ + row))*(3*D_) + c8*8);
            cp16(Vb_u + (row*72 + c8*8)*2,
                 Vrow + (size_t)row*S_ + c8*8);
        }
        cp_commit();
    }
    __syncthreads();

    // ---- preload Q fragments ----
    uint32_t aQ[4][4];
    {
        const uint32_t qoff = Ps_u + ((wq*16 + frow)*72 + fcol)*2;
        #pragma unroll
        for (int kk = 0; kk < 4; kk++)
            ldsm4(aQ[kk], qoff + kk*16*2);
    }

    float m[2], l[2], o[8][4];
    m[0] = m[1] = -1e30f; l[0] = l[1] = 0.f;
    #pragma unroll
    for (int ni = 0; ni < 8; ni++)
        #pragma unroll
        for (int r = 0; r < 4; r++) o[ni][r] = 0.f;

    const uint32_t kfoff = (frow*72 + fcol)*2;
    const int NT = S_/64;

    for (int kt = 0; kt < NT; kt++) {
        __syncthreads();   // all warps done with buffer (kt+1)&1 from iter kt-1
        if (kt + 1 < NT) {
            const uint32_t kb = Kb_u + (((kt+1)&1)*64*72)*2;
            const uint32_t vb = Vb_u + (((kt+1)&1)*64*72)*2;
            #pragma unroll
            for (int i = 0; i < 2; i++) {
                const int c = t + 256*i;
                const int row = c >> 3, c8 = c & 7;
                cp16(kb + (row*72 + c8*8)*2,
                     Kp + ((size_t)(b*S_ + (kt+1)*64 + row))*(3*D_) + c8*8);
                cp16(vb + (row*72 + c8*8)*2,
                     Vrow + (size_t)row*S_ + (kt+1)*64 + c8*8);
            }
        }
        cp_commit();
        cp_wait<1>();      // tile kt landed
        __syncthreads();

        const uint32_t Ks_u = Kb_u + ((kt&1)*64*72)*2;
        const uint32_t Vs_u = Vb_u + ((kt&1)*64*72)*2;

        // ---- S = Q K^T (raw, unscaled) ----
        float acc[8][4];
        #pragma unroll
        for (int ni = 0; ni < 8; ni++)
            #pragma unroll
            for (int r = 0; r < 4; r++) acc[ni][r] = 0.f;

        #pragma unroll
        for (int kk = 0; kk < 4; kk++) {
            #pragma unroll
            for (int j = 0; j < 4; j++) {
                uint32_t kq[4];
                ldsm4(kq, Ks_u + kfoff + (j*16*72 + kk*16)*2);
                uint32_t bf0[2] = { kq[0], kq[2] };
                uint32_t bf1[2] = { kq[1], kq[3] };
                mma_f16(acc[2*j],     aQ[kk], bf0);
                mma_f16(acc[2*j + 1], aQ[kk], bf1);
            }
        }

        // ---- online softmax in base-2 domain ----
        float tm0 = -1e30f, tm1 = -1e30f;
        #pragma unroll
        for (int ni = 0; ni < 8; ni++) {
            tm0 = fmaxf(tm0, fmaxf(acc[ni][0], acc[ni][1]));
            tm1 = fmaxf(tm1, fmaxf(acc[ni][2], acc[ni][3]));
        }
        #pragma unroll
        for (int off = 1; off < 4; off <<= 1) {
            tm0 = fmaxf(tm0, __shfl_xor_sync(0xffffffffu, tm0, off));
            tm1 = fmaxf(tm1, __shfl_xor_sync(0xffffffffu, tm1, off));
        }
        tm0 *= SCL2; tm1 *= SCL2;      // log2 domain
        const float mn0 = fmaxf(m[0], tm0);
        const float mn1 = fmaxf(m[1], tm1);
        const float corr0 = exp2f(m[0] - mn0);
        const float corr1 = exp2f(m[1] - mn1);
        float ts0 = 0.f, ts1 = 0.f;
        #pragma unroll
        for (int ni = 0; ni < 8; ni++) {
            acc[ni][0] = exp2f(fmaf(acc[ni][0], SCL2, -mn0));
            acc[ni][1] = exp2f(fmaf(acc[ni][1], SCL2, -mn0));
            acc[ni][2] = exp2f(fmaf(acc[ni][2], SCL2, -mn1));
            acc[ni][3] = exp2f(fmaf(acc[ni][3], SCL2, -mn1));
            ts0 += acc[ni][0] + acc[ni][1];
            ts1 += acc[ni][2] + acc[ni][3];
        }
        #pragma unroll
        for (int off = 1; off < 4; off <<= 1) {
            ts0 += __shfl_xor_sync(0xffffffffu, ts0, off);
            ts1 += __shfl_xor_sync(0xffffffffu, ts1, off);
        }
        l[0] = l[0]*corr0 + ts0;  m[0] = mn0;
        l[1] = l[1]*corr1 + ts1;  m[1] = mn1;
        #pragma unroll
        for (int ni = 0; ni < 8; ni++) {
            o[ni][0] *= corr0; o[ni][1] *= corr0;
            o[ni][2] *= corr1; o[ni][3] *= corr1;
        }

        // ---- O += P V : P fed directly from S registers (C-frag == A-frag) ----
        #pragma unroll
        for (int kk = 0; kk < 4; kk++) {
            uint32_t aP[4];
            aP[0] = f2h2(acc[2*kk    ][0], acc[2*kk    ][1]);   // row g,   keys 16kk+2tg..+1
            aP[1] = f2h2(acc[2*kk    ][2], acc[2*kk    ][3]);   // row g+8, keys 16kk+2tg..+1
            aP[2] = f2h2(acc[2*kk + 1][0], acc[2*kk + 1][1]);   // row g,   keys 16kk+8+2tg..
            aP[3] = f2h2(acc[2*kk + 1][2], acc[2*kk + 1][3]);   // row g+8, keys 16kk+8+2tg..
            #pragma unroll
            for (int j = 0; j < 4; j++) {
                uint32_t vq[4];
                ldsm4(vq, Vs_u + kfoff + (j*16*72 + kk*16)*2);
                uint32_t bf0[2] = { vq[0], vq[2] };
                uint32_t bf1[2] = { vq[1], vq[3] };
                mma_f16(o[2*j],     aP, bf0);
                mma_f16(o[2*j + 1], aP, bf1);
            }
        }
    }

    // ---- epilogue: O /= l, write half ctx ----
    const float inv0 = 1.0f / l[0];
    const float inv1 = 1.0f / l[1];
    const size_t row0 = (size_t)(b*S_ + qt*128 + wq*16 + g);
    const size_t row1 = row0 + 8;
    #pragma unroll
    for (int ni = 0; ni < 8; ni++) {
        const int col = ni*8 + 2*tg;
        *(__half2*)&O[row0*D_ + h*DH_ + col] = __floats2half2_rn(o[ni][0]*inv0, o[ni][1]*inv0);
        *(__half2*)&O[row1*D_ + h*DH_ + col] = __floats2half2_rn(o[ni][2]*inv1, o[ni][3]*inv1);
    }
}

// ---------------- host launcher ----------------
extern "C" void kernel_launch(void* const* d_in, const int* in_sizes, int n_in,
                              void* d_out, int out_size) {
    const float* fx  = (const float*)d_in[0];
    const float* px  = (const float*)d_in[1];
    const float* Wq  = (const float*)d_in[2];
    const float* bq  = (const float*)d_in[3];
    const float* Wk  = (const float*)d_in[4];
    const float* bk  = (const float*)d_in[5];
    const float* Wv  = (const float*)d_in[6];
    const float* bv  = (const float*)d_in[7];
    const float* Wo  = (const float*)d_in[8];
    const float* bo  = (const float*)d_in[9];
    const float* a1  = (const float*)d_in[10];
    const float* be1 = (const float*)d_in[11];
    const float* a2  = (const float*)d_in[12];
    const float* be2 = (const float*)d_in[13];
    const float* W1  = (const float*)d_in[14];
    const float* b1  = (const float*)d_in[15];
    const float* W2  = (const float*)d_in[16];
    const float* b2  = (const float*)d_in[17];
    const float* Wp  = (const float*)d_in[18];
    const float* bp  = (const float*)d_in[19];

    float* xo = (float*)d_out;                    // x: M_ x D_
    float* po = xo + (size_t)M_ * D_;             // p: M_ x P_

    float  *xn, *bqkv;
    __half *xnr, *qkv, *vt, *ctx, *x2h, *hbh, *xrh, *pxh;
    __half *wqkvT, *woT, *w1T, *w2T, *wpT;
    cudaGetSymbolAddress((void**)&xn,    g_xn);
    cudaGetSymbolAddress((void**)&xnr,   g_xnr);
    cudaGetSymbolAddress((void**)&qkv,   g_qkv);
    cudaGetSymbolAddress((void**)&vt,    g_vt);
    cudaGetSymbolAddress((void**)&ctx,   g_ctx);
    cudaGetSymbolAddress((void**)&x2h,   g_x2);
    cudaGetSymbolAddress((void**)&hbh,   g_hb);
    cudaGetSymbolAddress((void**)&xrh,   g_xr);
    cudaGetSymbolAddress((void**)&pxh,   g_pxh);
    cudaGetSymbolAddress((void**)&wqkvT, g_wqkvT);
    cudaGetSymbolAddress((void**)&woT,   g_woT);
    cudaGetSymbolAddress((void**)&w1T,   g_w1T);
    cudaGetSymbolAddress((void**)&w2T,   g_w2T);
    cudaGetSymbolAddress((void**)&wpT,   g_wpT);
    cudaGetSymbolAddress((void**)&bqkv,  g_bqkv);

    cudaFuncSetAttribute(attn_kernel, cudaFuncAttributeMaxDynamicSharedMemorySize, ATTN_SMEM);
    cudaFuncSetAttribute(hgemm<false,true,false>, cudaFuncAttributeMaxDynamicSharedMemorySize, GEMM_SMEM);
    cudaFuncSetAttribute(hgemm<false,true,true>,  cudaFuncAttributeMaxDynamicSharedMemorySize, GEMM_SMEM);
    cudaFuncSetAttribute(hgemm<true,true,false>,  cudaFuncAttributeMaxDynamicSharedMemorySize, GEMM_SMEM);

    // 0. weight transposes + conversions (one fused launch for all 7 weights)
    dim3 tb(32, 8);
    wtrans_all_kernel<<<dim3(32, 40, 7), tb>>>(Wq, Wk, Wv, Wo, W1, W2, Wp,
                                               wqkvT, woT, w1T, w2T, wpT);
    bcat_kernel<<<(3*D_)/256, 256>>>(bq, bk, bv, bqkv);
    hconv_kernel<<<(M_*P_)/1024, 256>>>(px, pxh, M_*P_);

    // 1. xn = LN1(feature_x): exact -> xn, half -> xnr
    ln_kernel<<<M_, 256>>>(fx, a1, be1, xn, xnr);

    // 2. fused QKV GEMM: [M][3072]
    hgemm<false,true,false><<<dim3(3*D_/256, M_/128), 256, GEMM_SMEM>>>(
        xnr, D_, nullptr, 0, wqkvT, bqkv, nullptr, nullptr, qkv, M_, 3*D_);

    // 2b. transpose V slice for PV mma
    vtrans_kernel<<<dim3(D_/32, S_/32, B_), tb>>>(qkv + 2*D_, vt);

    // 3. attention -> ctx (half)
    attn_kernel<<<dim3(S_/128, H_, B_), 256, ATTN_SMEM>>>(qkv, vt, ctx);

    // 4. x = xn + ctx@Wo + bo (f32 -> d_out)
    dim3 gD(D_/256, M_/128);
    hgemm<false,true,true><<<gD, 256, GEMM_SMEM>>>(
        ctx, D_, nullptr, 0, woT, bo, xn, xo, nullptr, M_, D_);

    // 5. x2 = LN2(x) (half only)
    ln_kernel<<<M_, 256>>>(xo, a2, be2, nullptr, x2h);

    // 6. h = relu(x2@W1+b1) (half); x = x + h@W2 + b2 (f32 -> d_out, half -> xrh)
    hgemm<true,true,false><<<dim3(DFF_/256, M_/128), 256, GEMM_SMEM>>>(
        x2h, D_, nullptr, 0, w1T, b1, nullptr, nullptr, hbh, M_, DFF_);
    hgemm<false,true,true><<<gD, 256, GEMM_SMEM>>>(
        hbh, DFF_, nullptr, 0, w2T, b2, xo, xo, xrh, M_, D_);

    // 7. p = [x, param_x] @ Wp + bp (single dual-A GEMM, K = 1024 + 256)
    hgemm<false,true,false><<<dim3(P_/256, M_/128), 256, GEMM_SMEM>>>(
        xrh, D_, pxh, P_, wpT, bp, nullptr, po, nullptr, M_, P_);
}

// round 13
// speedup vs baseline: 1.1042x; 1.0162x over previous
#include <cuda_runtime.h>
#include <cuda_fp16.h>
#include <cstdint>

// ---------------- problem constants ----------------
#define B_  4
#define S_  2048
#define D_  1024
#define P_  256
#define H_  16
#define DH_ 64
#define DFF_ 512
#define M_  (B_*S_)           // 8192 rows
#define EPS_ 1e-6f

// ---------------- scratch (static device globals; no allocation) ----------------
__device__ float  g_xn [M_*D_];          // exact LN1 output (residual)
__device__ __half g_xnr[M_*D_];          // half LN1 output (GEMM A)
__device__ __half g_qkv[M_*3*D_];        // fused QKV output [M][3072]
__device__ __half g_ctx[M_*D_];
__device__ __half g_x2 [M_*D_];
__device__ __half g_hb [M_*DFF_];
__device__ __half g_xr [M_*D_];          // half copy of final x (Wp input)
__device__ __half g_pxh[M_*P_];
__device__ __half g_wqkvT[3*D_*D_];      // [3072][1024]
__device__ __half g_woT[D_*D_];
__device__ __half g_w1T[D_*DFF_];
__device__ __half g_w2T[DFF_*D_];
__device__ __half g_wpT[P_*(D_+P_)];     // [256][1280]
__device__ float  g_bqkv[3*D_];

// ---------------- ptx helpers ----------------
__device__ __forceinline__ void mma_f16(float c[4], const uint32_t a[4], const uint32_t b[2]) {
    asm volatile(
        "mma.sync.aligned.m16n8k16.row.col.f32.f16.f16.f32 "
        "{%0,%1,%2,%3}, {%4,%5,%6,%7}, {%8,%9}, {%0,%1,%2,%3};\n"
        : "+f"(c[0]), "+f"(c[1]), "+f"(c[2]), "+f"(c[3])
        : "r"(a[0]), "r"(a[1]), "r"(a[2]), "r"(a[3]), "r"(b[0]), "r"(b[1]));
}

__device__ __forceinline__ void ldsm4(uint32_t r[4], uint32_t addr) {
    asm volatile("ldmatrix.sync.aligned.m8n8.x4.shared.b16 {%0,%1,%2,%3}, [%4];"
        : "=r"(r[0]), "=r"(r[1]), "=r"(r[2]), "=r"(r[3]) : "r"(addr));
}

__device__ __forceinline__ void ldsm4t(uint32_t r[4], uint32_t addr) {
    asm volatile("ldmatrix.sync.aligned.m8n8.x4.trans.shared.b16 {%0,%1,%2,%3}, [%4];"
        : "=r"(r[0]), "=r"(r[1]), "=r"(r[2]), "=r"(r[3]) : "r"(addr));
}

__device__ __forceinline__ uint32_t smem_u32(const void* p) {
    uint32_t a;
    asm("{ .reg .u64 t; cvta.to.shared.u64 t, %1; cvt.u32.u64 %0, t; }" : "=r"(a) : "l"(p));
    return a;
}

__device__ __forceinline__ void cp16(uint32_t dst, const void* src) {
    asm volatile("cp.async.ca.shared.global [%0], [%1], 16;" :: "r"(dst), "l"(src));
}
__device__ __forceinline__ void cp_commit() {
    asm volatile("cp.async.commit_group;" ::: "memory");
}
template<int N_>
__device__ __forceinline__ void cp_wait() {
    asm volatile("cp.async.wait_group %0;" :: "n"(N_) : "memory");
}

__device__ __forceinline__ uint32_t f2h2(float a, float b) {
    __half2 h = __floats2half2_rn(a, b);
    return *(uint32_t*)&h;
}

// ---------------- prep kernels ----------------
// Unified transpose+convert for all 7 weights: in[K][N] f32 -> out[N][K] half.
// z: 0 Wq, 1 Wk, 2 Wv (-> wqkvT slices), 3 Wo, 4 W1, 5 W2, 6 Wp.
__global__ void wtrans_all_kernel(const float* __restrict__ Wq, const float* __restrict__ Wk,
                                  const float* __restrict__ Wv, const float* __restrict__ Wo,
                                  const float* __restrict__ W1, const float* __restrict__ W2,
                                  const float* __restrict__ Wp,
                                  __half* __restrict__ oqkv, __half* __restrict__ owo,
                                  __half* __restrict__ ow1, __half* __restrict__ ow2,
                                  __half* __restrict__ owp) {
    const int z = blockIdx.z;
    const float* in; __half* out; int K, N;
    switch (z) {
        case 0: in = Wq; out = oqkv;             K = D_;    N = D_;   break;
        case 1: in = Wk; out = oqkv + D_*D_;     K = D_;    N = D_;   break;
        case 2: in = Wv; out = oqkv + 2*D_*D_;   K = D_;    N = D_;   break;
        case 3: in = Wo; out = owo;              K = D_;    N = D_;   break;
        case 4: in = W1; out = ow1;              K = D_;    N = DFF_; break;
        case 5: in = W2; out = ow2;              K = DFF_;  N = D_;   break;
        default:in = Wp; out = owp;              K = D_+P_; N = P_;   break;
    }
    const int n0 = blockIdx.x*32, k0 = blockIdx.y*32;
    if (n0 >= N || k0 >= K) return;
    __shared__ float tile[32][33];
    const int tx = threadIdx.x, ty = threadIdx.y;   // 32x8
    #pragma unroll
    for (int j = 0; j < 32; j += 8)
        tile[ty+j][tx] = in[(size_t)(k0+ty+j)*N + n0+tx];
    __syncthreads();
    #pragma unroll
    for (int j = 0; j < 32; j += 8)
        out[(size_t)(n0+ty+j)*K + k0+tx] = __float2half_rn(tile[tx][ty+j]);
}

__global__ void hconv_kernel(const float* __restrict__ in, __half* __restrict__ out, int n) {
    int i = (blockIdx.x * 256 + threadIdx.x) * 4;
    if (i < n) {
        float4 v = *(const float4*)(in + i);
        __half2* o2 = (__half2*)(out + i);
        o2[0] = __floats2half2_rn(v.x, v.y);
        o2[1] = __floats2half2_rn(v.z, v.w);
    }
}

__global__ void bcat_kernel(const float* __restrict__ bq, const float* __restrict__ bk,
                            const float* __restrict__ bv, float* __restrict__ out) {
    int i = blockIdx.x*256 + threadIdx.x;
    out[i] = (i < D_) ? bq[i] : (i < 2*D_) ? bk[i - D_] : bv[i - 2*D_];
}

// ---------------- LayerNorm: optional exact f32 + half output ----------------
__global__ void ln_kernel(const float* __restrict__ in,
                          const float* __restrict__ alpha,
                          const float* __restrict__ beta,
                          float* __restrict__ out,      // exact (nullable)
                          __half* __restrict__ outh) {  // half
    const int row = blockIdx.x;
    const int t = threadIdx.x;            // 256 threads, 4 elems each
    const float* x = in + (size_t)row * D_;
    float v[4];
    float s = 0.f;
    #pragma unroll
    for (int i = 0; i < 4; i++) { v[i] = x[t + 256*i]; s += v[i]; }

    __shared__ float red[8];
    #pragma unroll
    for (int o = 16; o > 0; o >>= 1) s += __shfl_xor_sync(0xffffffffu, s, o);
    if ((t & 31) == 0) red[t >> 5] = s;
    __syncthreads();
    float tot = 0.f;
    #pragma unroll
    for (int i = 0; i < 8; i++) tot += red[i];
    const float mu = tot * (1.0f / D_);

    float ss = 0.f;
    #pragma unroll
    for (int i = 0; i < 4; i++) { float d = v[i] - mu; ss += d * d; }
    __syncthreads();
    #pragma unroll
    for (int o = 16; o > 0; o >>= 1) ss += __shfl_xor_sync(0xffffffffu, ss, o);
    if ((t & 31) == 0) red[t >> 5] = ss;
    __syncthreads();
    float sst = 0.f;
    #pragma unroll
    for (int i = 0; i < 8; i++) sst += red[i];

    const float stdv = sqrtf(fmaxf(sst, 0.f) * (1.0f / (D_ - 1)));
    const float inv = 1.0f / (stdv + EPS_);
    float*  o  = out  ? out  + (size_t)row * D_ : nullptr;
    __half* oh = outh + (size_t)row * D_;
    #pragma unroll
    for (int i = 0; i < 4; i++) {
        int c = t + 256*i;
        const float y = alpha[c] * (v[i] - mu) * inv + beta[c];
        oh[c] = __float2half_rn(y);
        if (o) o[c] = y;
    }
}

// ---------------- fp16 mma GEMM: 128x256 CTA tile, 64-K chunks, 3-stage cp.async ----------------
#define SWW 36                    // smem row stride in words (72 halves, 144B)
#define ASTG (128*72)             // A stage halves
#define BSTG (256*72)             // B stage halves
#define STGH (ASTG + BSTG)        // halves per stage (27648)
#define GEMM_SMEM (3*STGH*2)      // 165888 bytes

template<bool RELU, bool HASBIAS, bool HASRES>
__global__ __launch_bounds__(256, 1)
void hgemm(const __half* __restrict__ A, int K1,
           const __half* __restrict__ A2, int K2,
           const __half* __restrict__ Bt,
           const float* __restrict__ bias, const float* __restrict__ res,
           float* __restrict__ C, __half* __restrict__ Ch,
           int M, int N) {
    extern __shared__ __half hsm[];
    const uint32_t sb = smem_u32(hsm);
    const int t = threadIdx.x;
    const int w = t >> 5, lane = t & 31;
    const int wm = w >> 2, wn = w & 3;       // warp grid 2 (m) x 4 (n), warp tile 64x64
    const int g = lane >> 2, tg = lane & 3;
    const int bx = blockIdx.x, by = blockIdx.y;

    // ldmatrix lane addressing
    const int quad = lane >> 3, lrow = lane & 7;
    const uint32_t frow = (quad & 1)*8 + lrow;
    const uint32_t fcol = (quad >> 1)*8;

    const int KB = K1 + K2;
    const int KT = KB >> 6, K1T = K1 >> 6;
    const __half* Ab  = A  + (size_t)by * 128 * K1;
    const __half* A2b = A2 ? A2 + (size_t)by * 128 * K2 : Ab;
    const __half* Bb  = Bt + (size_t)bx * 256 * KB;

    // prologue: stages 0,1
    #pragma unroll
    for (int s = 0; s < 2; s++) {
        const uint32_t as = sb + (s*STGH)*2;
        const uint32_t bs = as + ASTG*2;
        #pragma unroll
        for (int j = 0; j < 4; j++) {        // A: 1024 chunks
            const int c = t + 256*j;
            const int row = c >> 3, c8 = c & 7;
            const __half* asrc = (s < K1T) ? Ab + (size_t)row*K1 + s*64 + c8*8
                                           : A2b + (size_t)row*K2 + (s - K1T)*64 + c8*8;
            cp16(as + (row*72 + c8*8)*2, asrc);
        }
        #pragma unroll
        for (int j = 0; j < 8; j++) {        // B: 2048 chunks
            const int c = t + 256*j;
            const int row = c >> 3, c8 = c & 7;
            cp16(bs + (row*72 + c8*8)*2, Bb + (size_t)row*KB + s*64 + c8*8);
        }
        cp_commit();
    }

    float acc[4][8][4];
    #pragma unroll
    for (int mi = 0; mi < 4; mi++)
        #pragma unroll
        for (int ni = 0; ni < 8; ni++)
            #pragma unroll
            for (int r = 0; r < 4; r++) acc[mi][ni][r] = 0.f;

    for (int kt = 0; kt < KT; kt++) {
        // issue stage kt+2 first, then wait only for tile kt
        if (kt + 2 < KT) {
            const int kc = kt + 2;
            const int s = kc % 3;
            const uint32_t as = sb + (s*STGH)*2;
            const uint32_t bs = as + ASTG*2;
            #pragma unroll
            for (int j = 0; j < 4; j++) {
                const int c = t + 256*j;
                const int row = c >> 3, c8 = c & 7;
                const __half* asrc = (kc < K1T) ? Ab + (size_t)row*K1 + kc*64 + c8*8
                                                : A2b + (size_t)row*K2 + (kc - K1T)*64 + c8*8;
                cp16(as + (row*72 + c8*8)*2, asrc);
            }
            #pragma unroll
            for (int j = 0; j < 8; j++) {
                const int c = t + 256*j;
                const int row = c >> 3, c8 = c & 7;
                cp16(bs + (row*72 + c8*8)*2, Bb + (size_t)row*KB + kc*64 + c8*8);
            }
        }
        cp_commit();
        cp_wait<2>();          // tile kt complete; kt+1, kt+2 may still be in flight
        __syncthreads();

        const int cs = kt % 3;
        const uint32_t asb = sb + (cs*STGH)*2;
        const uint32_t bsb = asb + ASTG*2;
        const uint32_t aoff = asb + ((wm*64 + frow)*72 + fcol)*2;
        const uint32_t boff = bsb + ((wn*64 + frow)*72 + fcol)*2;
        #pragma unroll
        for (int kk = 0; kk < 4; kk++) {
            uint32_t af[4][4];
            #pragma unroll
            for (int mi = 0; mi < 4; mi++)
                ldsm4(af[mi], aoff + (mi*16*72 + kk*16)*2);
            uint32_t bqd[4][4];
            #pragma unroll
            for (int j = 0; j < 4; j++)
                ldsm4(bqd[j], boff + (j*16*72 + kk*16)*2);
            #pragma unroll
            for (int mi = 0; mi < 4; mi++) {
                #pragma unroll
                for (int j = 0; j < 4; j++) {
                    uint32_t bf0[2] = { bqd[j][0], bqd[j][2] };
                    uint32_t bf1[2] = { bqd[j][1], bqd[j][3] };
                    mma_f16(acc[mi][2*j],     af[mi], bf0);
                    mma_f16(acc[mi][2*j + 1], af[mi], bf1);
                }
            }
        }
        __syncthreads();   // all warps done with stage kt before it is overwritten (kt+3)
    }

    // epilogue
    #pragma unroll
    for (int mi = 0; mi < 4; mi++) {
        #pragma unroll
        for (int ni = 0; ni < 8; ni++) {
            const size_t row0 = (size_t)by*128 + wm*64 + mi*16 + g;
            const size_t row1 = row0 + 8;
            const int col = bx*256 + wn*64 + ni*8 + 2*tg;
            float v0 = acc[mi][ni][0], v1 = acc[mi][ni][1];
            float v2 = acc[mi][ni][2], v3 = acc[mi][ni][3];
            if (HASBIAS) {
                const float bb0 = bias[col], bb1 = bias[col+1];
                v0 += bb0; v1 += bb1; v2 += bb0; v3 += bb1;
            }
            if (HASRES) {
                v0 += res[row0*N + col]; v1 += res[row0*N + col + 1];
                v2 += res[row1*N + col]; v3 += res[row1*N + col + 1];
            }
            if (RELU) {
                v0 = fmaxf(v0, 0.f); v1 = fmaxf(v1, 0.f);
                v2 = fmaxf(v2, 0.f); v3 = fmaxf(v3, 0.f);
            }
            if (Ch) {
                *(__half2*)&Ch[row0*N + col] = __floats2half2_rn(v0, v1);
                *(__half2*)&Ch[row1*N + col] = __floats2half2_rn(v2, v3);
            }
            if (C) {
                *(float2*)&C[row0*N + col] = make_float2(v0, v1);
                *(float2*)&C[row1*N + col] = make_float2(v2, v3);
            }
        }
    }
}

// ---------------- fp16 flash attention: 256 threads (8 warps), 128 queries/CTA ----------------
// R12 structure; ONLY change: V used in natural [key][dh] layout straight from the
// fused QKV buffer, with ldmatrix.trans providing the k=key-paired B fragments.
// (trans of block (k-rows, n-cols) -> thread(g,tg) holds V[k0+2tg..+1][n0+g] = B-frag.)
#define ATTN_SMEM ((128 + 4*64) * 72 * 2)   // 55296 B
#define SCL2 0.18033688011112042f           // 0.125 * log2(e)

__global__ __launch_bounds__(256, 2)
void attn_kernel(const __half* __restrict__ QKV, __half* __restrict__ O) {
    extern __shared__ __half smh[];
    __half* Ps = smh;                     // [128][72] (Q staging only)
    __half* Kb = Ps + 128*72;             // [2][64][72]
    __half* Vb = Kb + 2*64*72;            // [2][64][72]  natural [key][dh]

    const int qt = blockIdx.x, h = blockIdx.y, b = blockIdx.z;
    const int t = threadIdx.x;
    const int wq = t >> 5, lane = t & 31;
    const int g = lane >> 2, tg = lane & 3;

    const int quad = lane >> 3, lrow = lane & 7;
    const uint32_t frow = (quad & 1)*8 + lrow;
    const uint32_t fcol = (quad >> 1)*8;

    const uint32_t Ps_u = smem_u32(Ps);
    const uint32_t Kb_u = smem_u32(Kb);
    const uint32_t Vb_u = smem_u32(Vb);

    const __half* Qp = QKV + (size_t)h*DH_;                    // stride 3*D_
    const __half* Kp = QKV + D_ + (size_t)h*DH_;
    const __half* Vp = QKV + 2*D_ + (size_t)h*DH_;

    // ---- stage Q tile [128][64] into Ps ----
    #pragma unroll
    for (int i = 0; i < 4; i++) {
        const int c = t + 256*i;        // 1024 chunks of 16B
        const int row = c >> 3, c8 = c & 7;
        *(uint4*)(Ps + row*72 + c8*8) =
            *(const uint4*)(Qp + ((size_t)(b*S_ + qt*128 + row))*(3*D_) + c8*8);
    }

    // ---- issue cp.async for K/V tile 0 (buffer 0) ----
    {
        #pragma unroll
        for (int i = 0; i < 2; i++) {
            const int c = t + 256*i;     // 512 chunks each
            const int row = c >> 3, c8 = c & 7;
            cp16(Kb_u + (row*72 + c8*8)*2,
                 Kp + ((size_t)(b*S_ + row))*(3*D_) + c8*8);
            cp16(Vb_u + (row*72 + c8*8)*2,
                 Vp + ((size_t)(b*S_ + row))*(3*D_) + c8*8);
        }
        cp_commit();
    }
    __syncthreads();

    // ---- preload Q fragments ----
    uint32_t aQ[4][4];
    {
        const uint32_t qoff = Ps_u + ((wq*16 + frow)*72 + fcol)*2;
        #pragma unroll
        for (int kk = 0; kk < 4; kk++)
            ldsm4(aQ[kk], qoff + kk*16*2);
    }

    float m[2], l[2], o[8][4];
    m[0] = m[1] = -1e30f; l[0] = l[1] = 0.f;
    #pragma unroll
    for (int ni = 0; ni < 8; ni++)
        #pragma unroll
        for (int r = 0; r < 4; r++) o[ni][r] = 0.f;

    const uint32_t kfoff = (frow*72 + fcol)*2;
    const int NT = S_/64;

    for (int kt = 0; kt < NT; kt++) {
        __syncthreads();   // all warps done with buffer (kt+1)&1 from iter kt-1
        if (kt + 1 < NT) {
            const uint32_t kb = Kb_u + (((kt+1)&1)*64*72)*2;
            const uint32_t vb = Vb_u + (((kt+1)&1)*64*72)*2;
            #pragma unroll
            for (int i = 0; i < 2; i++) {
                const int c = t + 256*i;
                const int row = c >> 3, c8 = c & 7;
                cp16(kb + (row*72 + c8*8)*2,
                     Kp + ((size_t)(b*S_ + (kt+1)*64 + row))*(3*D_) + c8*8);
                cp16(vb + (row*72 + c8*8)*2,
                     Vp + ((size_t)(b*S_ + (kt+1)*64 + row))*(3*D_) + c8*8);
            }
        }
        cp_commit();
        cp_wait<1>();      // tile kt landed
        __syncthreads();

        const uint32_t Ks_u = Kb_u + ((kt&1)*64*72)*2;
        const uint32_t Vs_u = Vb_u + ((kt&1)*64*72)*2;

        // ---- S = Q K^T (raw, unscaled) ----
        float acc[8][4];
        #pragma unroll
        for (int ni = 0; ni < 8; ni++)
            #pragma unroll
            for (int r = 0; r < 4; r++) acc[ni][r] = 0.f;

        #pragma unroll
        for (int kk = 0; kk < 4; kk++) {
            #pragma unroll
            for (int j = 0; j < 4; j++) {
                uint32_t kq[4];
                ldsm4(kq, Ks_u + kfoff + (j*16*72 + kk*16)*2);
                uint32_t bf0[2] = { kq[0], kq[2] };
                uint32_t bf1[2] = { kq[1], kq[3] };
                mma_f16(acc[2*j],     aQ[kk], bf0);
                mma_f16(acc[2*j + 1], aQ[kk], bf1);
            }
        }

        // ---- online softmax in base-2 domain ----
        float tm0 = -1e30f, tm1 = -1e30f;
        #pragma unroll
        for (int ni = 0; ni < 8; ni++) {
            tm0 = fmaxf(tm0, fmaxf(acc[ni][0], acc[ni][1]));
            tm1 = fmaxf(tm1, fmaxf(acc[ni][2], acc[ni][3]));
        }
        #pragma unroll
        for (int off = 1; off < 4; off <<= 1) {
            tm0 = fmaxf(tm0, __shfl_xor_sync(0xffffffffu, tm0, off));
            tm1 = fmaxf(tm1, __shfl_xor_sync(0xffffffffu, tm1, off));
        }
        tm0 *= SCL2; tm1 *= SCL2;      // log2 domain
        const float mn0 = fmaxf(m[0], tm0);
        const float mn1 = fmaxf(m[1], tm1);
        const float corr0 = exp2f(m[0] - mn0);
        const float corr1 = exp2f(m[1] - mn1);
        float ts0 = 0.f, ts1 = 0.f;
        #pragma unroll
        for (int ni = 0; ni < 8; ni++) {
            acc[ni][0] = exp2f(fmaf(acc[ni][0], SCL2, -mn0));
            acc[ni][1] = exp2f(fmaf(acc[ni][1], SCL2, -mn0));
            acc[ni][2] = exp2f(fmaf(acc[ni][2], SCL2, -mn1));
            acc[ni][3] = exp2f(fmaf(acc[ni][3], SCL2, -mn1));
            ts0 += acc[ni][0] + acc[ni][1];
            ts1 += acc[ni][2] + acc[ni][3];
        }
        #pragma unroll
        for (int off = 1; off < 4; off <<= 1) {
            ts0 += __shfl_xor_sync(0xffffffffu, ts0, off);
            ts1 += __shfl_xor_sync(0xffffffffu, ts1, off);
        }
        l[0] = l[0]*corr0 + ts0;  m[0] = mn0;
        l[1] = l[1]*corr1 + ts1;  m[1] = mn1;
        #pragma unroll
        for (int ni = 0; ni < 8; ni++) {
            o[ni][0] *= corr0; o[ni][1] *= corr0;
            o[ni][2] *= corr1; o[ni][3] *= corr1;
        }

        // ---- O += P V : P from S registers; V via ldmatrix.trans of natural tile ----
        #pragma unroll
        for (int kk = 0; kk < 4; kk++) {
            uint32_t aP[4];
            aP[0] = f2h2(acc[2*kk    ][0], acc[2*kk    ][1]);   // row g,   keys 16kk+2tg..+1
            aP[1] = f2h2(acc[2*kk    ][2], acc[2*kk    ][3]);   // row g+8, keys 16kk+2tg..+1
            aP[2] = f2h2(acc[2*kk + 1][0], acc[2*kk + 1][1]);   // row g,   keys 16kk+8+2tg..
            aP[3] = f2h2(acc[2*kk + 1][2], acc[2*kk + 1][3]);   // row g+8, keys 16kk+8+2tg..
            #pragma unroll
            for (int j = 0; j < 4; j++) {
                uint32_t vq[4];
                // rows = keys (kk block), cols = dh (j block); trans -> k-paired B frags
                ldsm4t(vq, Vs_u + kfoff + (kk*16*72 + j*16)*2);
                uint32_t bf0[2] = { vq[0], vq[1] };   // n = j*16 + 0..7
                uint32_t bf1[2] = { vq[2], vq[3] };   // n = j*16 + 8..15
                mma_f16(o[2*j],     aP, bf0);
                mma_f16(o[2*j + 1], aP, bf1);
            }
        }
    }

    // ---- epilogue: O /= l, write half ctx ----
    const float inv0 = 1.0f / l[0];
    const float inv1 = 1.0f / l[1];
    const size_t row0 = (size_t)(b*S_ + qt*128 + wq*16 + g);
    const size_t row1 = row0 + 8;
    #pragma unroll
    for (int ni = 0; ni < 8; ni++) {
        const int col = ni*8 + 2*tg;
        *(__half2*)&O[row0*D_ + h*DH_ + col] = __floats2half2_rn(o[ni][0]*inv0, o[ni][1]*inv0);
        *(__half2*)&O[row1*D_ + h*DH_ + col] = __floats2half2_rn(o[ni][2]*inv1, o[ni][3]*inv1);
    }
}

// ---------------- host launcher ----------------
extern "C" void kernel_launch(void* const* d_in, const int* in_sizes, int n_in,
                              void* d_out, int out_size) {
    const float* fx  = (const float*)d_in[0];
    const float* px  = (const float*)d_in[1];
    const float* Wq  = (const float*)d_in[2];
    const float* bq  = (const float*)d_in[3];
    const float* Wk  = (const float*)d_in[4];
    const float* bk  = (const float*)d_in[5];
    const float* Wv  = (const float*)d_in[6];
    const float* bv  = (const float*)d_in[7];
    const float* Wo  = (const float*)d_in[8];
    const float* bo  = (const float*)d_in[9];
    const float* a1  = (const float*)d_in[10];
    const float* be1 = (const float*)d_in[11];
    const float* a2  = (const float*)d_in[12];
    const float* be2 = (const float*)d_in[13];
    const float* W1  = (const float*)d_in[14];
    const float* b1  = (const float*)d_in[15];
    const float* W2  = (const float*)d_in[16];
    const float* b2  = (const float*)d_in[17];
    const float* Wp  = (const float*)d_in[18];
    const float* bp  = (const float*)d_in[19];

    float* xo = (float*)d_out;                    // x: M_ x D_
    float* po = xo + (size_t)M_ * D_;             // p: M_ x P_

    float  *xn, *bqkv;
    __half *xnr, *qkv, *ctx, *x2h, *hbh, *xrh, *pxh;
    __half *wqkvT, *woT, *w1T, *w2T, *wpT;
    cudaGetSymbolAddress((void**)&xn,    g_xn);
    cudaGetSymbolAddress((void**)&xnr,   g_xnr);
    cudaGetSymbolAddress((void**)&qkv,   g_qkv);
    cudaGetSymbolAddress((void**)&ctx,   g_ctx);
    cudaGetSymbolAddress((void**)&x2h,   g_x2);
    cudaGetSymbolAddress((void**)&hbh,   g_hb);
    cudaGetSymbolAddress((void**)&xrh,   g_xr);
    cudaGetSymbolAddress((void**)&pxh,   g_pxh);
    cudaGetSymbolAddress((void**)&wqkvT, g_wqkvT);
    cudaGetSymbolAddress((void**)&woT,   g_woT);
    cudaGetSymbolAddress((void**)&w1T,   g_w1T);
    cudaGetSymbolAddress((void**)&w2T,   g_w2T);
    cudaGetSymbolAddress((void**)&wpT,   g_wpT);
    cudaGetSymbolAddress((void**)&bqkv,  g_bqkv);

    cudaFuncSetAttribute(attn_kernel, cudaFuncAttributeMaxDynamicSharedMemorySize, ATTN_SMEM);
    cudaFuncSetAttribute(hgemm<false,true,false>, cudaFuncAttributeMaxDynamicSharedMemorySize, GEMM_SMEM);
    cudaFuncSetAttribute(hgemm<false,true,true>,  cudaFuncAttributeMaxDynamicSharedMemorySize, GEMM_SMEM);
    cudaFuncSetAttribute(hgemm<true,true,false>,  cudaFuncAttributeMaxDynamicSharedMemorySize, GEMM_SMEM);

    // 0. weight transposes + conversions (one fused launch for all 7 weights)
    dim3 tb(32, 8);
    wtrans_all_kernel<<<dim3(32, 40, 7), tb>>>(Wq, Wk, Wv, Wo, W1, W2, Wp,
                                               wqkvT, woT, w1T, w2T, wpT);
    bcat_kernel<<<(3*D_)/256, 256>>>(bq, bk, bv, bqkv);
    hconv_kernel<<<(M_*P_)/1024, 256>>>(px, pxh, M_*P_);

    // 1. xn = LN1(feature_x): exact -> xn, half -> xnr
    ln_kernel<<<M_, 256>>>(fx, a1, be1, xn, xnr);

    // 2. fused QKV GEMM: [M][3072]
    hgemm<false,true,false><<<dim3(3*D_/256, M_/128), 256, GEMM_SMEM>>>(
        xnr, D_, nullptr, 0, wqkvT, bqkv, nullptr, nullptr, qkv, M_, 3*D_);

    // 3. attention -> ctx (half); V consumed directly from qkv (no transpose)
    attn_kernel<<<dim3(S_/128, H_, B_), 256, ATTN_SMEM>>>(qkv, ctx);

    // 4. x = xn + ctx@Wo + bo (f32 -> d_out)
    dim3 gD(D_/256, M_/128);
    hgemm<false,true,true><<<gD, 256, GEMM_SMEM>>>(
        ctx, D_, nullptr, 0, woT, bo, xn, xo, nullptr, M_, D_);

    // 5. x2 = LN2(x) (half only)
    ln_kernel<<<M_, 256>>>(xo, a2, be2, nullptr, x2h);

    // 6. h = relu(x2@W1+b1) (half); x = x + h@W2 + b2 (f32 -> d_out, half -> xrh)
    hgemm<true,true,false><<<dim3(DFF_/256, M_/128), 256, GEMM_SMEM>>>(
        x2h, D_, nullptr, 0, w1T, b1, nullptr, nullptr, hbh, M_, DFF_);
    hgemm<false,true,true><<<gD, 256, GEMM_SMEM>>>(
        hbh, DFF_, nullptr, 0, w2T, b2, xo, xo, xrh, M_, D_);

    // 7. p = [x, param_x] @ Wp + bp (single dual-A GEMM, K = 1024 + 256)
    hgemm<false,true,false><<<dim3(P_/256, M_/128), 256, GEMM_SMEM>>>(
        xrh, D_, pxh, P_, wpT, bp, nullptr, po, nullptr, M_, P_);
}

// round 14
// speedup vs baseline: 1.1119x; 1.0070x over previous
#include <cuda_runtime.h>
#include <cuda_fp16.h>
#include <cstdint>

// ---------------- problem constants ----------------
#define B_  4
#define S_  2048
#define D_  1024
#define P_  256
#define H_  16
#define DH_ 64
#define DFF_ 512
#define M_  (B_*S_)           // 8192 rows
#define EPS_ 1e-6f

// ---------------- scratch (static device globals; no allocation) ----------------
__device__ float  g_xn [M_*D_];          // exact LN1 output (residual)
__device__ __half g_xnr[M_*D_];          // half LN1 output (GEMM A)
__device__ __half g_qkv[M_*3*D_];        // fused QKV output [M][3072]
__device__ __half g_ctx[M_*D_];
__device__ __half g_x2 [M_*D_];
__device__ __half g_hb [M_*DFF_];
__device__ __half g_xr [M_*D_];          // half copy of final x (Wp input)
__device__ __half g_pxh[M_*P_];
__device__ __half g_wqkvT[3*D_*D_];      // [3072][1024]
__device__ __half g_woT[D_*D_];
__device__ __half g_w1T[D_*DFF_];
__device__ __half g_w2T[DFF_*D_];
__device__ __half g_wpT[P_*(D_+P_)];     // [256][1280]
__device__ float  g_bqkv[3*D_];

// ---------------- ptx helpers ----------------
__device__ __forceinline__ void mma_f16(float c[4], const uint32_t a[4], const uint32_t b[2]) {
    asm volatile(
        "mma.sync.aligned.m16n8k16.row.col.f32.f16.f16.f32 "
        "{%0,%1,%2,%3}, {%4,%5,%6,%7}, {%8,%9}, {%0,%1,%2,%3};\n"
        : "+f"(c[0]), "+f"(c[1]), "+f"(c[2]), "+f"(c[3])
        : "r"(a[0]), "r"(a[1]), "r"(a[2]), "r"(a[3]), "r"(b[0]), "r"(b[1]));
}

__device__ __forceinline__ void ldsm4(uint32_t r[4], uint32_t addr) {
    asm volatile("ldmatrix.sync.aligned.m8n8.x4.shared.b16 {%0,%1,%2,%3}, [%4];"
        : "=r"(r[0]), "=r"(r[1]), "=r"(r[2]), "=r"(r[3]) : "r"(addr));
}

__device__ __forceinline__ void ldsm4t(uint32_t r[4], uint32_t addr) {
    asm volatile("ldmatrix.sync.aligned.m8n8.x4.trans.shared.b16 {%0,%1,%2,%3}, [%4];"
        : "=r"(r[0]), "=r"(r[1]), "=r"(r[2]), "=r"(r[3]) : "r"(addr));
}

__device__ __forceinline__ uint32_t smem_u32(const void* p) {
    uint32_t a;
    asm("{ .reg .u64 t; cvta.to.shared.u64 t, %1; cvt.u32.u64 %0, t; }" : "=r"(a) : "l"(p));
    return a;
}

__device__ __forceinline__ void cp16(uint32_t dst, const void* src) {
    asm volatile("cp.async.ca.shared.global [%0], [%1], 16;" :: "r"(dst), "l"(src));
}
__device__ __forceinline__ void cp_commit() {
    asm volatile("cp.async.commit_group;" ::: "memory");
}
template<int N_>
__device__ __forceinline__ void cp_wait() {
    asm volatile("cp.async.wait_group %0;" :: "n"(N_) : "memory");
}

__device__ __forceinline__ uint32_t f2h2(float a, float b) {
    __half2 h = __floats2half2_rn(a, b);
    return *(uint32_t*)&h;
}

// ---------------- prep kernels ----------------
// Unified transpose+convert for all 7 weights: in[K][N] f32 -> out[N][K] half.
// z: 0 Wq, 1 Wk, 2 Wv (-> wqkvT slices), 3 Wo, 4 W1, 5 W2, 6 Wp.
__global__ void wtrans_all_kernel(const float* __restrict__ Wq, const float* __restrict__ Wk,
                                  const float* __restrict__ Wv, const float* __restrict__ Wo,
                                  const float* __restrict__ W1, const float* __restrict__ W2,
                                  const float* __restrict__ Wp,
                                  __half* __restrict__ oqkv, __half* __restrict__ owo,
                                  __half* __restrict__ ow1, __half* __restrict__ ow2,
                                  __half* __restrict__ owp) {
    const int z = blockIdx.z;
    const float* in; __half* out; int K, N;
    switch (z) {
        case 0: in = Wq; out = oqkv;             K = D_;    N = D_;   break;
        case 1: in = Wk; out = oqkv + D_*D_;     K = D_;    N = D_;   break;
        case 2: in = Wv; out = oqkv + 2*D_*D_;   K = D_;    N = D_;   break;
        case 3: in = Wo; out = owo;              K = D_;    N = D_;   break;
        case 4: in = W1; out = ow1;              K = D_;    N = DFF_; break;
        case 5: in = W2; out = ow2;              K = DFF_;  N = D_;   break;
        default:in = Wp; out = owp;              K = D_+P_; N = P_;   break;
    }
    const int n0 = blockIdx.x*32, k0 = blockIdx.y*32;
    if (n0 >= N || k0 >= K) return;
    __shared__ float tile[32][33];
    const int tx = threadIdx.x, ty = threadIdx.y;   // 32x8
    #pragma unroll
    for (int j = 0; j < 32; j += 8)
        tile[ty+j][tx] = in[(size_t)(k0+ty+j)*N + n0+tx];
    __syncthreads();
    #pragma unroll
    for (int j = 0; j < 32; j += 8)
        out[(size_t)(n0+ty+j)*K + k0+tx] = __float2half_rn(tile[tx][ty+j]);
}

__global__ void hconv_kernel(const float* __restrict__ in, __half* __restrict__ out, int n) {
    int i = (blockIdx.x * 256 + threadIdx.x) * 4;
    if (i < n) {
        float4 v = *(const float4*)(in + i);
        __half2* o2 = (__half2*)(out + i);
        o2[0] = __floats2half2_rn(v.x, v.y);
        o2[1] = __floats2half2_rn(v.z, v.w);
    }
}

__global__ void bcat_kernel(const float* __restrict__ bq, const float* __restrict__ bk,
                            const float* __restrict__ bv, float* __restrict__ out) {
    int i = blockIdx.x*256 + threadIdx.x;
    out[i] = (i < D_) ? bq[i] : (i < 2*D_) ? bk[i - D_] : bv[i - 2*D_];
}

// ---------------- LayerNorm: optional exact f32 + half output ----------------
__global__ void ln_kernel(const float* __restrict__ in,
                          const float* __restrict__ alpha,
                          const float* __restrict__ beta,
                          float* __restrict__ out,      // exact (nullable)
                          __half* __restrict__ outh) {  // half
    const int row = blockIdx.x;
    const int t = threadIdx.x;            // 256 threads, 4 elems each
    const float* x = in + (size_t)row * D_;
    float v[4];
    float s = 0.f;
    #pragma unroll
    for (int i = 0; i < 4; i++) { v[i] = x[t + 256*i]; s += v[i]; }

    __shared__ float red[8];
    #pragma unroll
    for (int o = 16; o > 0; o >>= 1) s += __shfl_xor_sync(0xffffffffu, s, o);
    if ((t & 31) == 0) red[t >> 5] = s;
    __syncthreads();
    float tot = 0.f;
    #pragma unroll
    for (int i = 0; i < 8; i++) tot += red[i];
    const float mu = tot * (1.0f / D_);

    float ss = 0.f;
    #pragma unroll
    for (int i = 0; i < 4; i++) { float d = v[i] - mu; ss += d * d; }
    __syncthreads();
    #pragma unroll
    for (int o = 16; o > 0; o >>= 1) ss += __shfl_xor_sync(0xffffffffu, ss, o);
    if ((t & 31) == 0) red[t >> 5] = ss;
    __syncthreads();
    float sst = 0.f;
    #pragma unroll
    for (int i = 0; i < 8; i++) sst += red[i];

    const float stdv = sqrtf(fmaxf(sst, 0.f) * (1.0f / (D_ - 1)));
    const float inv = 1.0f / (stdv + EPS_);
    float*  o  = out  ? out  + (size_t)row * D_ : nullptr;
    __half* oh = outh + (size_t)row * D_;
    #pragma unroll
    for (int i = 0; i < 4; i++) {
        int c = t + 256*i;
        const float y = alpha[c] * (v[i] - mu) * inv + beta[c];
        oh[c] = __float2half_rn(y);
        if (o) o[c] = y;
    }
}

// ---------------- fp16 mma GEMM: 128x256 CTA tile, 64-K chunks, 3-stage cp.async ----------------
// Single barrier per k-iter: wait for tile kt, barrier, THEN issue kt+2 (which
// overwrites stage (kt-1)%3 — safe because every warp past the barrier has
// finished compute kt-1).
#define SWW 36                    // smem row stride in words (72 halves, 144B)
#define ASTG (128*72)             // A stage halves
#define BSTG (256*72)             // B stage halves
#define STGH (ASTG + BSTG)        // halves per stage (27648)
#define GEMM_SMEM (3*STGH*2)      // 165888 bytes

template<bool RELU, bool HASBIAS, bool HASRES>
__global__ __launch_bounds__(256, 1)
void hgemm(const __half* __restrict__ A, int K1,
           const __half* __restrict__ A2, int K2,
           const __half* __restrict__ Bt,
           const float* __restrict__ bias, const float* __restrict__ res,
           float* __restrict__ C, __half* __restrict__ Ch,
           int M, int N) {
    extern __shared__ __half hsm[];
    const uint32_t sb = smem_u32(hsm);
    const int t = threadIdx.x;
    const int w = t >> 5, lane = t & 31;
    const int wm = w >> 2, wn = w & 3;       // warp grid 2 (m) x 4 (n), warp tile 64x64
    const int g = lane >> 2, tg = lane & 3;
    const int bx = blockIdx.x, by = blockIdx.y;

    // ldmatrix lane addressing
    const int quad = lane >> 3, lrow = lane & 7;
    const uint32_t frow = (quad & 1)*8 + lrow;
    const uint32_t fcol = (quad >> 1)*8;

    const int KB = K1 + K2;
    const int KT = KB >> 6, K1T = K1 >> 6;
    const __half* Ab  = A  + (size_t)by * 128 * K1;
    const __half* A2b = A2 ? A2 + (size_t)by * 128 * K2 : Ab;
    const __half* Bb  = Bt + (size_t)bx * 256 * KB;

    // prologue: stages 0,1
    #pragma unroll
    for (int s = 0; s < 2; s++) {
        const uint32_t as = sb + (s*STGH)*2;
        const uint32_t bs = as + ASTG*2;
        #pragma unroll
        for (int j = 0; j < 4; j++) {        // A: 1024 chunks
            const int c = t + 256*j;
            const int row = c >> 3, c8 = c & 7;
            const __half* asrc = (s < K1T) ? Ab + (size_t)row*K1 + s*64 + c8*8
                                           : A2b + (size_t)row*K2 + (s - K1T)*64 + c8*8;
            cp16(as + (row*72 + c8*8)*2, asrc);
        }
        #pragma unroll
        for (int j = 0; j < 8; j++) {        // B: 2048 chunks
            const int c = t + 256*j;
            const int row = c >> 3, c8 = c & 7;
            cp16(bs + (row*72 + c8*8)*2, Bb + (size_t)row*KB + s*64 + c8*8);
        }
        cp_commit();
    }

    float acc[4][8][4];
    #pragma unroll
    for (int mi = 0; mi < 4; mi++)
        #pragma unroll
        for (int ni = 0; ni < 8; ni++)
            #pragma unroll
            for (int r = 0; r < 4; r++) acc[mi][ni][r] = 0.f;

    for (int kt = 0; kt < KT; kt++) {
        cp_wait<1>();          // pending = tiles kt, kt+1 -> tile kt landed
        __syncthreads();       // all warps done with compute kt-1; stage (kt-1)%3 free

        // issue stage kt+2 into stage (kt+2)%3 == (kt-1)%3
        if (kt + 2 < KT) {
            const int kc = kt + 2;
            const int s = kc % 3;
            const uint32_t as = sb + (s*STGH)*2;
            const uint32_t bs = as + ASTG*2;
            #pragma unroll
            for (int j = 0; j < 4; j++) {
                const int c = t + 256*j;
                const int row = c >> 3, c8 = c & 7;
                const __half* asrc = (kc < K1T) ? Ab + (size_t)row*K1 + kc*64 + c8*8
                                                : A2b + (size_t)row*K2 + (kc - K1T)*64 + c8*8;
                cp16(as + (row*72 + c8*8)*2, asrc);
            }
            #pragma unroll
            for (int j = 0; j < 8; j++) {
                const int c = t + 256*j;
                const int row = c >> 3, c8 = c & 7;
                cp16(bs + (row*72 + c8*8)*2, Bb + (size_t)row*KB + kc*64 + c8*8);
            }
        }
        cp_commit();

        const int cs = kt % 3;
        const uint32_t asb = sb + (cs*STGH)*2;
        const uint32_t bsb = asb + ASTG*2;
        const uint32_t aoff = asb + ((wm*64 + frow)*72 + fcol)*2;
        const uint32_t boff = bsb + ((wn*64 + frow)*72 + fcol)*2;
        #pragma unroll
        for (int kk = 0; kk < 4; kk++) {
            uint32_t af[4][4];
            #pragma unroll
            for (int mi = 0; mi < 4; mi++)
                ldsm4(af[mi], aoff + (mi*16*72 + kk*16)*2);
            uint32_t bqd[4][4];
            #pragma unroll
            for (int j = 0; j < 4; j++)
                ldsm4(bqd[j], boff + (j*16*72 + kk*16)*2);
            #pragma unroll
            for (int mi = 0; mi < 4; mi++) {
                #pragma unroll
                for (int j = 0; j < 4; j++) {
                    uint32_t bf0[2] = { bqd[j][0], bqd[j][2] };
                    uint32_t bf1[2] = { bqd[j][1], bqd[j][3] };
                    mma_f16(acc[mi][2*j],     af[mi], bf0);
                    mma_f16(acc[mi][2*j + 1], af[mi], bf1);
                }
            }
        }
    }

    // epilogue
    #pragma unroll
    for (int mi = 0; mi < 4; mi++) {
        #pragma unroll
        for (int ni = 0; ni < 8; ni++) {
            const size_t row0 = (size_t)by*128 + wm*64 + mi*16 + g;
            const size_t row1 = row0 + 8;
            const int col = bx*256 + wn*64 + ni*8 + 2*tg;
            float v0 = acc[mi][ni][0], v1 = acc[mi][ni][1];
            float v2 = acc[mi][ni][2], v3 = acc[mi][ni][3];
            if (HASBIAS) {
                const float bb0 = bias[col], bb1 = bias[col+1];
                v0 += bb0; v1 += bb1; v2 += bb0; v3 += bb1;
            }
            if (HASRES) {
                v0 += res[row0*N + col]; v1 += res[row0*N + col + 1];
                v2 += res[row1*N + col]; v3 += res[row1*N + col + 1];
            }
            if (RELU) {
                v0 = fmaxf(v0, 0.f); v1 = fmaxf(v1, 0.f);
                v2 = fmaxf(v2, 0.f); v3 = fmaxf(v3, 0.f);
            }
            if (Ch) {
                *(__half2*)&Ch[row0*N + col] = __floats2half2_rn(v0, v1);
                *(__half2*)&Ch[row1*N + col] = __floats2half2_rn(v2, v3);
            }
            if (C) {
                *(float2*)&C[row0*N + col] = make_float2(v0, v1);
                *(float2*)&C[row1*N + col] = make_float2(v2, v3);
            }
        }
    }
}

// ---------------- fp16 flash attention: 256 threads (8 warps), 128 queries/CTA ----------------
// (identical to R13)
#define ATTN_SMEM ((128 + 4*64) * 72 * 2)   // 55296 B
#define SCL2 0.18033688011112042f           // 0.125 * log2(e)

__global__ __launch_bounds__(256, 2)
void attn_kernel(const __half* __restrict__ QKV, __half* __restrict__ O) {
    extern __shared__ __half smh[];
    __half* Ps = smh;                     // [128][72] (Q staging only)
    __half* Kb = Ps + 128*72;             // [2][64][72]
    __half* Vb = Kb + 2*64*72;            // [2][64][72]  natural [key][dh]

    const int qt = blockIdx.x, h = blockIdx.y, b = blockIdx.z;
    const int t = threadIdx.x;
    const int wq = t >> 5, lane = t & 31;
    const int g = lane >> 2, tg = lane & 3;

    const int quad = lane >> 3, lrow = lane & 7;
    const uint32_t frow = (quad & 1)*8 + lrow;
    const uint32_t fcol = (quad >> 1)*8;

    const uint32_t Ps_u = smem_u32(Ps);
    const uint32_t Kb_u = smem_u32(Kb);
    const uint32_t Vb_u = smem_u32(Vb);

    const __half* Qp = QKV + (size_t)h*DH_;                    // stride 3*D_
    const __half* Kp = QKV + D_ + (size_t)h*DH_;
    const __half* Vp = QKV + 2*D_ + (size_t)h*DH_;

    // ---- stage Q tile [128][64] into Ps ----
    #pragma unroll
    for (int i = 0; i < 4; i++) {
        const int c = t + 256*i;        // 1024 chunks of 16B
        const int row = c >> 3, c8 = c & 7;
        *(uint4*)(Ps + row*72 + c8*8) =
            *(const uint4*)(Qp + ((size_t)(b*S_ + qt*128 + row))*(3*D_) + c8*8);
    }

    // ---- issue cp.async for K/V tile 0 (buffer 0) ----
    {
        #pragma unroll
        for (int i = 0; i < 2; i++) {
            const int c = t + 256*i;     // 512 chunks each
            const int row = c >> 3, c8 = c & 7;
            cp16(Kb_u + (row*72 + c8*8)*2,
                 Kp + ((size_t)(b*S_ + row))*(3*D_) + c8*8);
            cp16(Vb_u + (row*72 + c8*8)*2,
                 Vp + ((size_t)(b*S_ + row))*(3*D_) + c8*8);
        }
        cp_commit();
    }
    __syncthreads();

    // ---- preload Q fragments ----
    uint32_t aQ[4][4];
    {
        const uint32_t qoff = Ps_u + ((wq*16 + frow)*72 + fcol)*2;
        #pragma unroll
        for (int kk = 0; kk < 4; kk++)
            ldsm4(aQ[kk], qoff + kk*16*2);
    }

    float m[2], l[2], o[8][4];
    m[0] = m[1] = -1e30f; l[0] = l[1] = 0.f;
    #pragma unroll
    for (int ni = 0; ni < 8; ni++)
        #pragma unroll
        for (int r = 0; r < 4; r++) o[ni][r] = 0.f;

    const uint32_t kfoff = (frow*72 + fcol)*2;
    const int NT = S_/64;

    for (int kt = 0; kt < NT; kt++) {
        __syncthreads();   // all warps done with buffer (kt+1)&1 from iter kt-1
        if (kt + 1 < NT) {
            const uint32_t kb = Kb_u + (((kt+1)&1)*64*72)*2;
            const uint32_t vb = Vb_u + (((kt+1)&1)*64*72)*2;
            #pragma unroll
            for (int i = 0; i < 2; i++) {
                const int c = t + 256*i;
                const int row = c >> 3, c8 = c & 7;
                cp16(kb + (row*72 + c8*8)*2,
                     Kp + ((size_t)(b*S_ + (kt+1)*64 + row))*(3*D_) + c8*8);
                cp16(vb + (row*72 + c8*8)*2,
                     Vp + ((size_t)(b*S_ + (kt+1)*64 + row))*(3*D_) + c8*8);
            }
        }
        cp_commit();
        cp_wait<1>();      // tile kt landed
        __syncthreads();

        const uint32_t Ks_u = Kb_u + ((kt&1)*64*72)*2;
        const uint32_t Vs_u = Vb_u + ((kt&1)*64*72)*2;

        // ---- S = Q K^T (raw, unscaled) ----
        float acc[8][4];
        #pragma unroll
        for (int ni = 0; ni < 8; ni++)
            #pragma unroll
            for (int r = 0; r < 4; r++) acc[ni][r] = 0.f;

        #pragma unroll
        for (int kk = 0; kk < 4; kk++) {
            #pragma unroll
            for (int j = 0; j < 4; j++) {
                uint32_t kq[4];
                ldsm4(kq, Ks_u + kfoff + (j*16*72 + kk*16)*2);
                uint32_t bf0[2] = { kq[0], kq[2] };
                uint32_t bf1[2] = { kq[1], kq[3] };
                mma_f16(acc[2*j],     aQ[kk], bf0);
                mma_f16(acc[2*j + 1], aQ[kk], bf1);
            }
        }

        // ---- online softmax in base-2 domain ----
        float tm0 = -1e30f, tm1 = -1e30f;
        #pragma unroll
        for (int ni = 0; ni < 8; ni++) {
            tm0 = fmaxf(tm0, fmaxf(acc[ni][0], acc[ni][1]));
            tm1 = fmaxf(tm1, fmaxf(acc[ni][2], acc[ni][3]));
        }
        #pragma unroll
        for (int off = 1; off < 4; off <<= 1) {
            tm0 = fmaxf(tm0, __shfl_xor_sync(0xffffffffu, tm0, off));
            tm1 = fmaxf(tm1, __shfl_xor_sync(0xffffffffu, tm1, off));
        }
        tm0 *= SCL2; tm1 *= SCL2;      // log2 domain
        const float mn0 = fmaxf(m[0], tm0);
        const float mn1 = fmaxf(m[1], tm1);
        const float corr0 = exp2f(m[0] - mn0);
        const float corr1 = exp2f(m[1] - mn1);
        float ts0 = 0.f, ts1 = 0.f;
        #pragma unroll
        for (int ni = 0; ni < 8; ni++) {
            acc[ni][0] = exp2f(fmaf(acc[ni][0], SCL2, -mn0));
            acc[ni][1] = exp2f(fmaf(acc[ni][1], SCL2, -mn0));
            acc[ni][2] = exp2f(fmaf(acc[ni][2], SCL2, -mn1));
            acc[ni][3] = exp2f(fmaf(acc[ni][3], SCL2, -mn1));
            ts0 += acc[ni][0] + acc[ni][1];
            ts1 += acc[ni][2] + acc[ni][3];
        }
        #pragma unroll
        for (int off = 1; off < 4; off <<= 1) {
            ts0 += __shfl_xor_sync(0xffffffffu, ts0, off);
            ts1 += __shfl_xor_sync(0xffffffffu, ts1, off);
        }
        l[0] = l[0]*corr0 + ts0;  m[0] = mn0;
        l[1] = l[1]*corr1 + ts1;  m[1] = mn1;
        #pragma unroll
        for (int ni = 0; ni < 8; ni++) {
            o[ni][0] *= corr0; o[ni][1] *= corr0;
            o[ni][2] *= corr1; o[ni][3] *= corr1;
        }

        // ---- O += P V : P from S registers; V via ldmatrix.trans of natural tile ----
        #pragma unroll
        for (int kk = 0; kk < 4; kk++) {
            uint32_t aP[4];
            aP[0] = f2h2(acc[2*kk    ][0], acc[2*kk    ][1]);
            aP[1] = f2h2(acc[2*kk    ][2], acc[2*kk    ][3]);
            aP[2] = f2h2(acc[2*kk + 1][0], acc[2*kk + 1][1]);
            aP[3] = f2h2(acc[2*kk + 1][2], acc[2*kk + 1][3]);
            #pragma unroll
            for (int j = 0; j < 4; j++) {
                uint32_t vq[4];
                ldsm4t(vq, Vs_u + kfoff + (kk*16*72 + j*16)*2);
                uint32_t bf0[2] = { vq[0], vq[1] };
                uint32_t bf1[2] = { vq[2], vq[3] };
                mma_f16(o[2*j],     aP, bf0);
                mma_f16(o[2*j + 1], aP, bf1);
            }
        }
    }

    // ---- epilogue: O /= l, write half ctx ----
    const float inv0 = 1.0f / l[0];
    const float inv1 = 1.0f / l[1];
    const size_t row0 = (size_t)(b*S_ + qt*128 + wq*16 + g);
    const size_t row1 = row0 + 8;
    #pragma unroll
    for (int ni = 0; ni < 8; ni++) {
        const int col = ni*8 + 2*tg;
        *(__half2*)&O[row0*D_ + h*DH_ + col] = __floats2half2_rn(o[ni][0]*inv0, o[ni][1]*inv0);
        *(__half2*)&O[row1*D_ + h*DH_ + col] = __floats2half2_rn(o[ni][2]*inv1, o[ni][3]*inv1);
    }
}

// ---------------- host launcher ----------------
extern "C" void kernel_launch(void* const* d_in, const int* in_sizes, int n_in,
                              void* d_out, int out_size) {
    const float* fx  = (const float*)d_in[0];
    const float* px  = (const float*)d_in[1];
    const float* Wq  = (const float*)d_in[2];
    const float* bq  = (const float*)d_in[3];
    const float* Wk  = (const float*)d_in[4];
    const float* bk  = (const float*)d_in[5];
    const float* Wv  = (const float*)d_in[6];
    const float* bv  = (const float*)d_in[7];
    const float* Wo  = (const float*)d_in[8];
    const float* bo  = (const float*)d_in[9];
    const float* a1  = (const float*)d_in[10];
    const float* be1 = (const float*)d_in[11];
    const float* a2  = (const float*)d_in[12];
    const float* be2 = (const float*)d_in[13];
    const float* W1  = (const float*)d_in[14];
    const float* b1  = (const float*)d_in[15];
    const float* W2  = (const float*)d_in[16];
    const float* b2  = (const float*)d_in[17];
    const float* Wp  = (const float*)d_in[18];
    const float* bp  = (const float*)d_in[19];

    float* xo = (float*)d_out;                    // x: M_ x D_
    float* po = xo + (size_t)M_ * D_;             // p: M_ x P_

    float  *xn, *bqkv;
    __half *xnr, *qkv, *ctx, *x2h, *hbh, *xrh, *pxh;
    __half *wqkvT, *woT, *w1T, *w2T, *wpT;
    cudaGetSymbolAddress((void**)&xn,    g_xn);
    cudaGetSymbolAddress((void**)&xnr,   g_xnr);
    cudaGetSymbolAddress((void**)&qkv,   g_qkv);
    cudaGetSymbolAddress((void**)&ctx,   g_ctx);
    cudaGetSymbolAddress((void**)&x2h,   g_x2);
    cudaGetSymbolAddress((void**)&hbh,   g_hb);
    cudaGetSymbolAddress((void**)&xrh,   g_xr);
    cudaGetSymbolAddress((void**)&pxh,   g_pxh);
    cudaGetSymbolAddress((void**)&wqkvT, g_wqkvT);
    cudaGetSymbolAddress((void**)&woT,   g_woT);
    cudaGetSymbolAddress((void**)&w1T,   g_w1T);
    cudaGetSymbolAddress((void**)&w2T,   g_w2T);
    cudaGetSymbolAddress((void**)&wpT,   g_wpT);
    cudaGetSymbolAddress((void**)&bqkv,  g_bqkv);

    cudaFuncSetAttribute(attn_kernel, cudaFuncAttributeMaxDynamicSharedMemorySize, ATTN_SMEM);
    cudaFuncSetAttribute(hgemm<false,true,false>, cudaFuncAttributeMaxDynamicSharedMemorySize, GEMM_SMEM);
    cudaFuncSetAttribute(hgemm<false,true,true>,  cudaFuncAttributeMaxDynamicSharedMemorySize, GEMM_SMEM);
    cudaFuncSetAttribute(hgemm<true,true,false>,  cudaFuncAttributeMaxDynamicSharedMemorySize, GEMM_SMEM);

    // 0. weight transposes + conversions (one fused launch for all 7 weights)
    dim3 tb(32, 8);
    wtrans_all_kernel<<<dim3(32, 40, 7), tb>>>(Wq, Wk, Wv, Wo, W1, W2, Wp,
                                               wqkvT, woT, w1T, w2T, wpT);
    bcat_kernel<<<(3*D_)/256, 256>>>(bq, bk, bv, bqkv);
    hconv_kernel<<<(M_*P_)/1024, 256>>>(px, pxh, M_*P_);

    // 1. xn = LN1(feature_x): exact -> xn, half -> xnr
    ln_kernel<<<M_, 256>>>(fx, a1, be1, xn, xnr);

    // 2. fused QKV GEMM: [M][3072]
    hgemm<false,true,false><<<dim3(3*D_/256, M_/128), 256, GEMM_SMEM>>>(
        xnr, D_, nullptr, 0, wqkvT, bqkv, nullptr, nullptr, qkv, M_, 3*D_);

    // 3. attention -> ctx (half); V consumed directly from qkv (no transpose)
    attn_kernel<<<dim3(S_/128, H_, B_), 256, ATTN_SMEM>>>(qkv, ctx);

    // 4. x = xn + ctx@Wo + bo (f32 -> d_out)
    dim3 gD(D_/256, M_/128);
    hgemm<false,true,true><<<gD, 256, GEMM_SMEM>>>(
        ctx, D_, nullptr, 0, woT, bo, xn, xo, nullptr, M_, D_);

    // 5. x2 = LN2(x) (half only)
    ln_kernel<<<M_, 256>>>(xo, a2, be2, nullptr, x2h);

    // 6. h = relu(x2@W1+b1) (half); x = x + h@W2 + b2 (f32 -> d_out, half -> xrh)
    hgemm<true,true,false><<<dim3(DFF_/256, M_/128), 256, GEMM_SMEM>>>(
        x2h, D_, nullptr, 0, w1T, b1, nullptr, nullptr, hbh, M_, DFF_);
    hgemm<false,true,true><<<gD, 256, GEMM_SMEM>>>(
        hbh, DFF_, nullptr, 0, w2T, b2, xo, xo, xrh, M_, D_);

    // 7. p = [x, param_x] @ Wp + bp (single dual-A GEMM, K = 1024 + 256)
    hgemm<false,true,false><<<dim3(P_/256, M_/128), 256, GEMM_SMEM>>>(
        xrh, D_, pxh, P_, wpT, bp, nullptr, po, nullptr, M_, P_);
}